// round 14
// baseline (speedup 1.0000x reference)
#include <cuda_runtime.h>
#include <cuda_fp16.h>
#include <cstdint>
#include <cstddef>

#define PTOT (16*64*64)   // 65536 pixels, NHWC (C fastest)

// ---------------------------------------------------------------------------
// Device globals (no cudaMalloc allowed)
// ---------------------------------------------------------------------------
__device__ float g_Veff[256*256];
__device__ float g_ceff[256];
__device__ __half g_Y1h[(size_t)PTOT*256];
__device__ float g_Y2[(size_t)PTOT*256];
__device__ float g_base[(size_t)PTOT*64];
__device__ float g_Acc[(size_t)PTOT*64];
__device__ __half g_Dh0[(size_t)PTOT*64];
__device__ __half g_Dh1[(size_t)PTOT*64];
__device__ __half g_Bbuf[158*4096];           // fp16 hi/lo weight tiles

// ---------------------------------------------------------------------------
// PTX helpers (sm_80-compatible only; ptxas here targets plain sm_103)
// ---------------------------------------------------------------------------
__device__ __forceinline__ uint32_t s2u(const void* p) {
    uint32_t a;
    asm("{ .reg .u64 t; cvta.to.shared.u64 t, %1; cvt.u32.u64 %0, t; }"
        : "=r"(a) : "l"(p));
    return a;
}
#define SW128(o) ((uint32_t)(o) ^ (((uint32_t)(o) >> 3) & 0x70u))

__device__ __forceinline__ void cpa16(uint32_t dst, const void* src, bool valid) {
    asm volatile("cp.async.ca.shared.global [%0], [%1], 16, %2;"
                 :: "r"(dst), "l"(src), "r"(valid ? 16 : 0) : "memory");
}
__device__ __forceinline__ void cpa_commit() {
    asm volatile("cp.async.commit_group;" ::: "memory");
}
template<int N> __device__ __forceinline__ void cpa_wait() {
    asm volatile("cp.async.wait_group %0;" :: "n"(N) : "memory");
}

__device__ __forceinline__ void ldsm4(uint32_t* r, uint32_t addr) {
    asm volatile("ldmatrix.sync.aligned.m8n8.x4.shared.b16 {%0,%1,%2,%3}, [%4];"
                 : "=r"(r[0]), "=r"(r[1]), "=r"(r[2]), "=r"(r[3]) : "r"(addr));
}
__device__ __forceinline__ void mma_f16(float* c, const uint32_t* a, const uint32_t* b) {
    asm volatile(
        "mma.sync.aligned.m16n8k16.row.col.f32.f16.f16.f32 "
        "{%0,%1,%2,%3}, {%4,%5,%6,%7}, {%8,%9}, {%0,%1,%2,%3};"
        : "+f"(c[0]), "+f"(c[1]), "+f"(c[2]), "+f"(c[3])
        : "r"(a[0]), "r"(a[1]), "r"(a[2]), "r"(a[3]), "r"(b[0]), "r"(b[1]));
}
__device__ __forceinline__ uint32_t packh2(float a, float b) {
    __half2 h = __floats2half2_rn(a, b);
    return *reinterpret_cast<uint32_t*>(&h);
}

// ---------------------------------------------------------------------------
// Step1 composition in ONE kernel. One warp per row; state in registers.
// ---------------------------------------------------------------------------
#define COMPOSE_SMEM (64*256*4 + 64*4)
__global__ void __launch_bounds__(256)
compose_kernel(const float* __restrict__ w1, const float* __restrict__ b1)
{
    extern __shared__ float sh[];
    float* w1t = sh;
    float* b1s = sh + 64*256;
    const int tid = threadIdx.x;
    const int lane = tid & 31;

#pragma unroll
    for (int it = 0; it < 64; ++it) {
        const int id = it * 256 + tid;
        const int m = id >> 6, n = id & 63;
        w1t[n*256 + m] = w1[id];
    }
    if (tid < 64) b1s[tid] = b1[tid];
    __syncthreads();

    const int gw = blockIdx.x * 8 + (tid >> 5);
    if (gw > 256) return;
    const bool isC = (gw == 256);
    const int j = gw;

    float v[8], ex[2];
#pragma unroll
    for (int q = 0; q < 2; ++q)
        ex[q] = isC ? b1s[lane + 32*q] : w1[j*64 + lane + 32*q];
    v[0] = ex[0]; v[1] = ex[1];
    v[2]=v[3]=v[4]=v[5]=v[6]=v[7] = 0.f;

#pragma unroll
    for (int i = 1; i < 4; ++i) {
        const bool addEx = isC || (j >= 64 * i);
#pragma unroll 8
        for (int n = 0; n < 64; ++n) {
            float p = 0.f;
#pragma unroll
            for (int q = 0; q < 8; ++q)
                if (q < 2*i) p = fmaf(v[q], w1t[n*256 + lane + 32*q], p);
#pragma unroll
            for (int o = 16; o > 0; o >>= 1)
                p += __shfl_xor_sync(0xffffffffu, p, o);
            if (lane == (n & 31))
                v[2*i + (n >> 5)] = p + (addEx ? ex[n >> 5] : 0.f);
        }
    }

    if (isC) {
#pragma unroll
        for (int q = 0; q < 8; ++q) g_ceff[lane + 32*q] = v[q];
    } else {
#pragma unroll
        for (int q = 0; q < 8; ++q) g_Veff[j*256 + lane + 32*q] = v[q];
    }
}

// ---------------------------------------------------------------------------
// Weight prep: transpose + fp16-split + pre-swizzle all B tiles into g_Bbuf.
// ---------------------------------------------------------------------------
__global__ void wprep_kernel(const float* __restrict__ w2)
{
    const int b = blockIdx.x;
    const int tid = threadIdx.x;
    for (int it = 0; it < 16; ++it) {
        const int id = it * 256 + tid;
        const int n = id >> 6, k = id & 63;
        float val; int split;
        if (b < 32) {
            split = b >> 4; const int rem = b & 15;
            const int kc = rem >> 2, nt = rem & 3;
            val = g_Veff[(kc*64 + k)*256 + nt*64 + n];
        } else if (b < 104) {
            const int e = b - 32; split = e / 36; const int r = e % 36;
            const int t = r >> 2, kc = r & 3;
            val = w2[(size_t)t*16384 + (size_t)(kc*64 + k)*64 + n];
        } else {
            const int e = b - 104; const int j = e / 18; const int r = e % 18;
            split = r / 9; const int t = r % 9;
            val = w2[(size_t)t*16384 + (size_t)(j*64 + k)*64 + n];
        }
        const __half h = __float2half_rn(val);
        const __half l = __float2half_rn(val - __half2float(h));
        *reinterpret_cast<__half*>(
            reinterpret_cast<char*>(g_Bbuf) + (size_t)b*8192 + SW128(n*128 + k*2))
            = (split == 0) ? h : l;
    }
}

// ===========================================================================
// PHASE 1: Y1 = relu(x @ Veff + ceff)   (1x1 conv, K=256, grid 512 x 4)
// xcvt FUSED: A staged via LDG(float4)+cvt+STS, software-pipelined so the
// LDG latency of chunk cc+1 hides under MMA(cc). B via cp.async as before.
// ===========================================================================
#define SMEM1 98304
__device__ __forceinline__ uint32_t o1A(int buf) {
    return (uint32_t)buf*49152u;
}
__device__ __forceinline__ uint32_t o1B(int buf, int split) {
    return (uint32_t)buf*49152u + 32768u + (uint32_t)split*8192u;
}

__global__ void __launch_bounds__(256, 2)
mma_p1(const float* __restrict__ X,
       const float* __restrict__ bias)
{
    extern __shared__ char smem[];
    const uint32_t sb = s2u(smem);
    const int tid = threadIdx.x;
    const int lane = tid & 31;
    const int wid = tid >> 5;
    const int pxBase = blockIdx.x * 128;
    const int nt0 = blockIdx.y;
    const int n0 = nt0 * 64;
    const int wpx = (wid >> 1) * 32;
    const int wn  = (wid & 1) * 32;

    float c[2][4][4];
#pragma unroll
    for (int mt = 0; mt < 2; ++mt)
#pragma unroll
        for (int nt = 0; nt < 4; ++nt)
#pragma unroll
            for (int e = 0; e < 4; ++e) c[mt][nt][e] = 0.f;

    float4 xr[4][2];
    auto ldgA = [&](int cidx) {
#pragma unroll
        for (int it = 0; it < 4; ++it) {
            const int id = it * 256 + tid;
            const int r = id >> 3, u = id & 7;
            const long off = (long)(pxBase + r) * 256 + cidx*64 + u*8;
            xr[it][0] = *reinterpret_cast<const float4*>(X + off);
            xr[it][1] = *reinterpret_cast<const float4*>(X + off + 4);
        }
    };
    auto stsA = [&](int buf) {
#pragma unroll
        for (int it = 0; it < 4; ++it) {
            const int id = it * 256 + tid;
            const int r = id >> 3, u = id & 7;
            uint4 v;
            v.x = packh2(xr[it][0].x, xr[it][0].y);
            v.y = packh2(xr[it][0].z, xr[it][0].w);
            v.z = packh2(xr[it][1].x, xr[it][1].y);
            v.w = packh2(xr[it][1].z, xr[it][1].w);
            *reinterpret_cast<uint4*>(smem + o1A(buf) + SW128(r*128 + u*16)) = v;
        }
    };
    auto stageB = [&](int cidx, int buf) {
        const __half* bsH = g_Bbuf + (size_t)(cidx*4 + nt0) * 4096;
        const __half* bsL = g_Bbuf + (size_t)(16 + cidx*4 + nt0) * 4096;
#pragma unroll
        for (int it = 0; it < 2; ++it) {
            const int id = it * 256 + tid;
            cpa16(sb + o1B(buf,0) + id*16, bsH + id*8, true);
            cpa16(sb + o1B(buf,1) + id*16, bsL + id*8, true);
        }
        cpa_commit();
    };

    // prologue
    ldgA(0);
    stageB(0, 0);
    stsA(0);

#pragma unroll 1
    for (int cc = 0; cc < 4; ++cc) {
        if (cc + 1 < 4) {
            ldgA(cc + 1);                       // latency hides under MMA(cc)
            stageB(cc + 1, (cc + 1) & 1);
            cpa_wait<1>();
        } else {
            cpa_wait<0>();
        }
        __syncthreads();

        const int buf = cc & 1;
        const uint32_t aBa = sb + o1A(buf);
        const uint32_t bHi = sb + o1B(buf,0), bLo = sb + o1B(buf,1);

#pragma unroll
        for (int ks = 0; ks < 4; ++ks) {
            uint32_t ah[2][4], bh[4][2], bl[4][2];
            {
                const int arow = wpx + ((lane >> 3) & 1) * 8 + (lane & 7);
                const int ak   = ks * 16 + (lane >> 4) * 8;
#pragma unroll
                for (int mt = 0; mt < 2; ++mt) {
                    const uint32_t asw = SW128((arow + mt*16) * 128 + ak * 2);
                    ldsm4(ah[mt], aBa + asw);
                }
            }
            {
                const int m = lane >> 3, r = lane & 7;
#pragma unroll
                for (int np = 0; np < 2; ++np) {
                    const int brow = wn + np*16 + (m >> 1) * 8 + r;
                    const int bk   = ks * 16 + (m & 1) * 8;
                    const uint32_t bsw = SW128(brow * 128 + bk * 2);
                    uint32_t rg[4];
                    ldsm4(rg, bHi + bsw);
                    bh[np*2+0][0] = rg[0]; bh[np*2+0][1] = rg[1];
                    bh[np*2+1][0] = rg[2]; bh[np*2+1][1] = rg[3];
                    ldsm4(rg, bLo + bsw);
                    bl[np*2+0][0] = rg[0]; bl[np*2+0][1] = rg[1];
                    bl[np*2+1][0] = rg[2]; bl[np*2+1][1] = rg[3];
                }
            }
#pragma unroll
            for (int mt = 0; mt < 2; ++mt)
#pragma unroll
                for (int nt = 0; nt < 4; ++nt) {
                    mma_f16(c[mt][nt], ah[mt], bh[nt]);
                    mma_f16(c[mt][nt], ah[mt], bl[nt]);
                }
        }
        if (cc + 1 < 4) stsA((cc + 1) & 1);     // data arrived during MMA
        __syncthreads();
    }

    const int g = lane >> 2, tq = lane & 3;
#pragma unroll
    for (int mt = 0; mt < 2; ++mt)
#pragma unroll
        for (int rh = 0; rh < 2; ++rh) {
            const size_t px = (size_t)pxBase + wpx + mt*16 + rh*8 + g;
#pragma unroll
            for (int nt = 0; nt < 4; ++nt) {
                const int ch = wn + nt*8 + tq*2;
                const float r0 = fmaxf(c[mt][nt][rh*2+0] + bias[n0+ch],   0.f);
                const float r1 = fmaxf(c[mt][nt][rh*2+1] + bias[n0+ch+1], 0.f);
                *reinterpret_cast<__half2*>(&g_Y1h[px*256 + n0 + ch]) =
                    __floats2half2_rn(r0, r1);
            }
        }
}

// ===========================================================================
// PHASE 2: 3x3 conv, CIN=256, HALO staging, flat 36-iter pipeline (R12).
// ===========================================================================
#define SMEM3 100352
#define A3BUF 33792u
__device__ __forceinline__ uint32_t o3B(int buf, int split) {
    return 67584u + (uint32_t)buf*16384u + (uint32_t)split*8192u;
}

__global__ void __launch_bounds__(256)
mma_p2(const __half* __restrict__ A,
       const float* __restrict__ bias,
       __half* __restrict__ DOut)
{
    extern __shared__ char smem[];
    const uint32_t sb = s2u(smem);
    const int tid = threadIdx.x;
    const int lane = tid & 31;
    const int wid = tid >> 5;
    const int pxBase = blockIdx.x * 128;
    const int y0 = (pxBase >> 6) & 63;
    const int img = pxBase >> 12;
    const int wpx = (wid >> 1) * 32;
    const int wn  = (wid & 1) * 32;

    float c[2][4][4];
#pragma unroll
    for (int mt = 0; mt < 2; ++mt)
#pragma unroll
        for (int nt = 0; nt < 4; ++nt)
#pragma unroll
            for (int e = 0; e < 4; ++e) c[mt][nt][e] = 0.f;

    auto stageA = [&](int kc, int abuf) {
#pragma unroll 1
        for (int it = 0; it < 9; ++it) {
            const int id = it * 256 + tid;
            if (id < 2112) {
                const int r = id >> 3, u = id & 7;
                const int row = r / 66;
                const int xt  = r - row * 66;
                const int y = y0 - 1 + row;
                const int x = xt - 1;
                const bool valid = ((unsigned)y < 64u) && ((unsigned)x < 64u);
                const long off = valid
                    ? ((long)(img*4096 + y*64 + x) * 256 + kc*64 + u*8) : 0L;
                cpa16(sb + abuf*A3BUF + SW128(r*128 + u*16), A + off, valid);
            }
        }
    };

    auto stageB = [&](int q, int buf) {
        const int kc = q / 9, t = q - kc * 9;
        const __half* bsH = g_Bbuf + (size_t)(32 + t*4 + kc) * 4096;
        const __half* bsL = g_Bbuf + (size_t)(68 + t*4 + kc) * 4096;
#pragma unroll
        for (int it = 0; it < 2; ++it) {
            const int id = it * 256 + tid;
            cpa16(sb + o3B(buf,0) + id*16, bsH + id*8, true);
            cpa16(sb + o3B(buf,1) + id*16, bsL + id*8, true);
        }
    };

    stageA(0, 0);
    stageB(0, 0);
    cpa_commit();

#pragma unroll 1
    for (int q = 0; q < 36; ++q) {
        const int kc = q / 9, t = q - kc * 9;
        if (q + 1 < 36) {
            stageB(q + 1, (q + 1) & 1);
            if (t == 0 && kc + 1 < 4) stageA(kc + 1, (kc + 1) & 1);
            cpa_commit();
            cpa_wait<1>();
        } else {
            cpa_wait<0>();
        }
        __syncthreads();

        const int dy = t / 3 - 1;
        const int dx = t % 3 - 1;
        const uint32_t aBa = sb + (kc & 1) * A3BUF;
        const uint32_t bHi = sb + o3B(q & 1, 0), bLo = sb + o3B(q & 1, 1);

#pragma unroll
        for (int ks = 0; ks < 4; ++ks) {
            uint32_t ah[2][4], bh[4][2], bl[4][2];
            {
                const int arow = wpx + ((lane >> 3) & 1) * 8 + (lane & 7);
                const int ak   = ks * 16 + (lane >> 4) * 8;
#pragma unroll
                for (int mt = 0; mt < 2; ++mt) {
                    const int ar = arow + mt*16;
                    const int tpx = ((ar >> 6) + dy + 1) * 66 + (ar & 63) + dx + 1;
                    ldsm4(ah[mt], aBa + SW128(tpx * 128 + ak * 2));
                }
            }
            {
                const int m = lane >> 3, r = lane & 7;
#pragma unroll
                for (int np = 0; np < 2; ++np) {
                    const int brow = wn + np*16 + (m >> 1) * 8 + r;
                    const int bk   = ks * 16 + (m & 1) * 8;
                    const uint32_t bsw = SW128(brow * 128 + bk * 2);
                    uint32_t rg[4];
                    ldsm4(rg, bHi + bsw);
                    bh[np*2+0][0] = rg[0]; bh[np*2+0][1] = rg[1];
                    bh[np*2+1][0] = rg[2]; bh[np*2+1][1] = rg[3];
                    ldsm4(rg, bLo + bsw);
                    bl[np*2+0][0] = rg[0]; bl[np*2+0][1] = rg[1];
                    bl[np*2+1][0] = rg[2]; bl[np*2+1][1] = rg[3];
                }
            }
#pragma unroll
            for (int mt = 0; mt < 2; ++mt)
#pragma unroll
                for (int nt = 0; nt < 4; ++nt) {
                    mma_f16(c[mt][nt], ah[mt], bh[nt]);
                    mma_f16(c[mt][nt], ah[mt], bl[nt]);
                }
        }
        __syncthreads();
    }

    const int g = lane >> 2, tq = lane & 3;
#pragma unroll
    for (int mt = 0; mt < 2; ++mt) {
#pragma unroll
        for (int rh = 0; rh < 2; ++rh) {
            const size_t px = (size_t)pxBase + wpx + mt*16 + rh*8 + g;
#pragma unroll
            for (int nt = 0; nt < 4; ++nt) {
                const int ch = wn + nt*8 + tq*2;
                const float r0 = c[mt][nt][rh*2 + 0] + bias[ch];
                const float r1 = c[mt][nt][rh*2 + 1] + bias[ch+1];
                float2 rr; rr.x = r0; rr.y = r1;
                *reinterpret_cast<float2*>(&g_base[px*64 + ch]) = rr;
                *reinterpret_cast<float2*>(&g_Y2[px*256 + ch])  = rr;
                const __half2 y = *reinterpret_cast<const __half2*>(&g_Y1h[px*256 + ch]);
                const float dd0 = r0 - __half2float(y.x);
                const float dd1 = r1 - __half2float(y.y);
                *reinterpret_cast<__half2*>(&DOut[px*64 + ch]) =
                    __floats2half2_rn(dd0, dd1);
            }
        }
    }
}

// ===========================================================================
// CORRECTIONS: 3x3 conv, CIN=64, SINGLE-TERM fp16 (weights hi only).
// smem: A halo [0,33792) B hi tiles double-buffered [33792 + buf*8192)
// 50176 bytes -> up to 3 CTAs/SM.
// ===========================================================================
#define SMEMC 50176
__device__ __forceinline__ uint32_t oCB(int buf) {
    return 33792u + (uint32_t)buf*8192u;
}

__global__ void __launch_bounds__(256)
mma_corr(const __half* __restrict__ A,
         __half* __restrict__ DOut,
         int jblk, int accumPrev)
{
    extern __shared__ char smem[];
    const uint32_t sb = s2u(smem);
    const int tid = threadIdx.x;
    const int lane = tid & 31;
    const int wid = tid >> 5;
    const int pxBase = blockIdx.x * 128;
    const int y0 = (pxBase >> 6) & 63;
    const int img = pxBase >> 12;
    const int wpx = (wid >> 1) * 32;
    const int wn  = (wid & 1) * 32;

    float c[2][4][4];
#pragma unroll
    for (int mt = 0; mt < 2; ++mt)
#pragma unroll
        for (int nt = 0; nt < 4; ++nt)
#pragma unroll
            for (int e = 0; e < 4; ++e) c[mt][nt][e] = 0.f;

    // stage A halo (CIN=64, single fp16)
#pragma unroll 1
    for (int it = 0; it < 9; ++it) {
        const int id = it * 256 + tid;
        if (id < 2112) {
            const int r = id >> 3, u = id & 7;
            const int row = r / 66;
            const int xt  = r - row * 66;
            const int y = y0 - 1 + row;
            const int x = xt - 1;
            const bool valid = ((unsigned)y < 64u) && ((unsigned)x < 64u);
            const long off = valid
                ? ((long)(img*4096 + y*64 + x) * 64 + u*8) : 0L;
            cpa16(sb + SW128(r*128 + u*16), A + off, valid);
        }
    }

    auto stageB = [&](int t, int buf) {
        const __half* bsH = g_Bbuf + (size_t)(104 + jblk*18 + t) * 4096;
#pragma unroll
        for (int it = 0; it < 2; ++it) {
            const int id = it * 256 + tid;
            cpa16(sb + oCB(buf) + id*16, bsH + id*8, true);
        }
    };

    stageB(0, 0);
    cpa_commit();
#pragma unroll 1
    for (int t = 0; t < 9; ++t) {
        if (t < 8) { stageB(t + 1, (t + 1) & 1); cpa_commit(); cpa_wait<1>(); }
        else       { cpa_wait<0>(); }
        __syncthreads();

        const int dy = t / 3 - 1;
        const int dx = t % 3 - 1;
        const uint32_t bHi = sb + oCB(t & 1);

#pragma unroll
        for (int ks = 0; ks < 4; ++ks) {
            uint32_t ah[2][4], bh[4][2];
            {
                const int arow = wpx + ((lane >> 3) & 1) * 8 + (lane & 7);
                const int ak   = ks * 16 + (lane >> 4) * 8;
#pragma unroll
                for (int mt = 0; mt < 2; ++mt) {
                    const int ar = arow + mt*16;
                    const int tpx = ((ar >> 6) + dy + 1) * 66 + (ar & 63) + dx + 1;
                    ldsm4(ah[mt], sb + SW128(tpx * 128 + ak * 2));
                }
            }
            {
                const int m = lane >> 3, r = lane & 7;
#pragma unroll
                for (int np = 0; np < 2; ++np) {
                    const int brow = wn + np*16 + (m >> 1) * 8 + r;
                    const int bk   = ks * 16 + (m & 1) * 8;
                    uint32_t rg[4];
                    ldsm4(rg, bHi + SW128(brow * 128 + bk * 2));
                    bh[np*2+0][0] = rg[0]; bh[np*2+0][1] = rg[1];
                    bh[np*2+1][0] = rg[2]; bh[np*2+1][1] = rg[3];
                }
            }
#pragma unroll
            for (int mt = 0; mt < 2; ++mt)
#pragma unroll
                for (int nt = 0; nt < 4; ++nt)
                    mma_f16(c[mt][nt], ah[mt], bh[nt]);
        }
        __syncthreads();
    }

    // ---- epilogue (corrections) ----
    const int g = lane >> 2, tq = lane & 3;
#pragma unroll
    for (int mt = 0; mt < 2; ++mt) {
#pragma unroll
        for (int rh = 0; rh < 2; ++rh) {
            const size_t px = (size_t)pxBase + wpx + mt*16 + rh*8 + g;
#pragma unroll
            for (int nt = 0; nt < 4; ++nt) {
                const int ch = wn + nt*8 + tq*2;
                float r0 = c[mt][nt][rh*2 + 0];
                float r1 = c[mt][nt][rh*2 + 1];
                if (accumPrev) {
                    const float2 a = *reinterpret_cast<const float2*>(&g_Acc[px*64 + ch]);
                    r0 += a.x; r1 += a.y;
                }
                float2 rr; rr.x = r0; rr.y = r1;
                *reinterpret_cast<float2*>(&g_Acc[px*64 + ch]) = rr;
                const float2 b = *reinterpret_cast<const float2*>(&g_base[px*64 + ch]);
                const float z0 = b.x + r0, z1 = b.y + r1;
                float2 zz; zz.x = z0; zz.y = z1;
                *reinterpret_cast<float2*>(&g_Y2[px*256 + (jblk+1)*64 + ch]) = zz;
                if (jblk < 2) {
                    const __half2 y = *reinterpret_cast<const __half2*>(
                        &g_Y1h[px*256 + (jblk+1)*64 + ch]);
                    const float dd0 = z0 - __half2float(y.x);
                    const float dd1 = z1 - __half2float(y.y);
                    *reinterpret_cast<__half2*>(&DOut[px*64 + ch]) =
                        __floats2half2_rn(dd0, dd1);
                }
            }
        }
    }
}

// ---------------------------------------------------------------------------
// Step3: per-pixel scalar recurrence (replaces 256 sequential 1x1 convs)
// ---------------------------------------------------------------------------
__global__ void __launch_bounds__(256)
step3_kernel(const float* __restrict__ x,
             const float* __restrict__ w3,
             const float* __restrict__ b3,
             float* __restrict__ out)
{
    __shared__ float sA[32][257];
    __shared__ float sw[256];
    const int tid = threadIdx.x;
    const size_t pBase = (size_t)blockIdx.x * 32;
    sw[tid] = w3[tid];

#pragma unroll
    for (int it = 0; it < 8; ++it) {
        const int g = it * 256 + tid;
        const int px = g >> 6;
        const int c = (g & 63) * 4;
        const float4 v = *reinterpret_cast<const float4*>(g_Y2 + (pBase + px)*256 + c);
        sA[px][c + 0] = fmaxf(v.x, 0.f);
        sA[px][c + 1] = fmaxf(v.y, 0.f);
        sA[px][c + 2] = fmaxf(v.z, 0.f);
        sA[px][c + 3] = fmaxf(v.w, 0.f);
    }
    __syncthreads();

    if (tid < 32) {
        float dot = 0.f;
#pragma unroll 8
        for (int c = 0; c < 256; ++c) dot = fmaf(sA[tid][c], sw[c], dot);
        const float bb = b3[0];
#pragma unroll 1
        for (int i = 0; i < 256; ++i) {
            const float a = sA[tid][i];
            const float z = dot + bb;
            sA[tid][i] = z;
            dot = fmaf(z - a, sw[i], dot);
        }
    }
    __syncthreads();

#pragma unroll
    for (int it = 0; it < 8; ++it) {
        const int g = it * 256 + tid;
        const int px = g >> 6;
        const int c = (g & 63) * 4;
        const float4 xv = *reinterpret_cast<const float4*>(x + (pBase + px)*256 + c);
        float4 r;
        r.x = sA[px][c + 0] + xv.x;
        r.y = sA[px][c + 1] + xv.y;
        r.z = sA[px][c + 2] + xv.z;
        r.w = sA[px][c + 3] + xv.w;
        *reinterpret_cast<float4*>(out + (pBase + px)*256 + c) = r;
    }
}

// ---------------------------------------------------------------------------
// Launch
// ---------------------------------------------------------------------------
extern "C" void kernel_launch(void* const* d_in, const int* in_sizes, int n_in,
                              void* d_out, int out_size)
{
    const float* x  = (const float*)d_in[0];
    const float* w1 = (const float*)d_in[1];
    const float* b1 = (const float*)d_in[2];
    const float* w2 = (const float*)d_in[3];
    const float* b2 = (const float*)d_in[4];
    const float* w3 = (const float*)d_in[5];
    const float* b3 = (const float*)d_in[6];
    float* out = (float*)d_out;

    __half *Y1h, *Dh0, *Dh1;
    float *ceff;
    cudaGetSymbolAddress((void**)&Y1h,  g_Y1h);
    cudaGetSymbolAddress((void**)&Dh0,  g_Dh0);
    cudaGetSymbolAddress((void**)&Dh1,  g_Dh1);
    cudaGetSymbolAddress((void**)&ceff, g_ceff);

    cudaFuncSetAttribute(compose_kernel,
                         cudaFuncAttributeMaxDynamicSharedMemorySize, COMPOSE_SMEM);
    cudaFuncSetAttribute(mma_p1,
                         cudaFuncAttributeMaxDynamicSharedMemorySize, SMEM1);
    cudaFuncSetAttribute(mma_p2,
                         cudaFuncAttributeMaxDynamicSharedMemorySize, SMEM3);
    cudaFuncSetAttribute(mma_corr,
                         cudaFuncAttributeMaxDynamicSharedMemorySize, SMEMC);

    // Phase 0: compose step1 weights; prep B tiles (xcvt fused into p1)
    compose_kernel<<<33, 256, COMPOSE_SMEM>>>(w1, b1);
    wprep_kernel<<<158, 256>>>(w2);

    // Phase 1: Y1 = relu(x @ Veff + ceff)   (converts x->fp16 inline)
    mma_p1<<<dim3(512, 4), 256, SMEM1>>>(x, ceff);

    // Phase 2: base = conv3x3(Y1, W2) + b2; Y2 blk0; D0
    mma_p2<<<512, 256, SMEM3>>>(Y1h, b2, Dh0);

    // Corrections: Z_{j+1} = base + sum_{m<=j} conv3x3(D_m, W2_blk_m)
    for (int j = 0; j < 3; ++j) {
        const __half* Ain = (j & 1) ? Dh1 : Dh0;
        __half*       Dn  = (j & 1) ? Dh0 : Dh1;
        mma_corr<<<512, 256, SMEMC>>>(Ain, Dn, j, (j > 0) ? 1 : 0);
    }

    // Phase 3: per-pixel recurrence + residual
    step3_kernel<<<2048, 256>>>(x, w3, b3, out);
}

// round 15
// speedup vs baseline: 1.1151x; 1.1151x over previous
#include <cuda_runtime.h>
#include <cuda_fp16.h>
#include <cstdint>
#include <cstddef>

#define PTOT (16*64*64)   // 65536 pixels, NHWC (C fastest)

// ---------------------------------------------------------------------------
// Device globals (no cudaMalloc allowed)
// ---------------------------------------------------------------------------
__device__ float g_Veff[256*256];
__device__ float g_ceff[256];
__device__ __half g_Y1h[(size_t)PTOT*256];
__device__ float g_Y2[(size_t)PTOT*256];
__device__ float g_base[(size_t)PTOT*64];
__device__ float g_Acc[(size_t)PTOT*64];
__device__ __half g_Dh0[(size_t)PTOT*64];
__device__ __half g_Dh1[(size_t)PTOT*64];
__device__ __half g_Bbuf[158*4096];           // fp16 hi/lo weight tiles

// ---------------------------------------------------------------------------
// PTX helpers (sm_80-compatible only; ptxas here targets plain sm_103)
// ---------------------------------------------------------------------------
__device__ __forceinline__ uint32_t s2u(const void* p) {
    uint32_t a;
    asm("{ .reg .u64 t; cvta.to.shared.u64 t, %1; cvt.u32.u64 %0, t; }"
        : "=r"(a) : "l"(p));
    return a;
}
#define SW128(o) ((uint32_t)(o) ^ (((uint32_t)(o) >> 3) & 0x70u))

__device__ __forceinline__ void cpa16(uint32_t dst, const void* src, bool valid) {
    asm volatile("cp.async.ca.shared.global [%0], [%1], 16, %2;"
                 :: "r"(dst), "l"(src), "r"(valid ? 16 : 0) : "memory");
}
__device__ __forceinline__ void cpa_commit() {
    asm volatile("cp.async.commit_group;" ::: "memory");
}
template<int N> __device__ __forceinline__ void cpa_wait() {
    asm volatile("cp.async.wait_group %0;" :: "n"(N) : "memory");
}

__device__ __forceinline__ void ldsm4(uint32_t* r, uint32_t addr) {
    asm volatile("ldmatrix.sync.aligned.m8n8.x4.shared.b16 {%0,%1,%2,%3}, [%4];"
                 : "=r"(r[0]), "=r"(r[1]), "=r"(r[2]), "=r"(r[3]) : "r"(addr));
}
__device__ __forceinline__ void mma_f16(float* c, const uint32_t* a, const uint32_t* b) {
    asm volatile(
        "mma.sync.aligned.m16n8k16.row.col.f32.f16.f16.f32 "
        "{%0,%1,%2,%3}, {%4,%5,%6,%7}, {%8,%9}, {%0,%1,%2,%3};"
        : "+f"(c[0]), "+f"(c[1]), "+f"(c[2]), "+f"(c[3])
        : "r"(a[0]), "r"(a[1]), "r"(a[2]), "r"(a[3]), "r"(b[0]), "r"(b[1]));
}
__device__ __forceinline__ uint32_t packh2(float a, float b) {
    __half2 h = __floats2half2_rn(a, b);
    return *reinterpret_cast<uint32_t*>(&h);
}

// ---------------------------------------------------------------------------
// Step1 composition in ONE kernel. One warp per row; state in registers.
// ---------------------------------------------------------------------------
#define COMPOSE_SMEM (64*256*4 + 64*4)
__global__ void __launch_bounds__(256)
compose_kernel(const float* __restrict__ w1, const float* __restrict__ b1)
{
    extern __shared__ float sh[];
    float* w1t = sh;
    float* b1s = sh + 64*256;
    const int tid = threadIdx.x;
    const int lane = tid & 31;

#pragma unroll
    for (int it = 0; it < 64; ++it) {
        const int id = it * 256 + tid;
        const int m = id >> 6, n = id & 63;
        w1t[n*256 + m] = w1[id];
    }
    if (tid < 64) b1s[tid] = b1[tid];
    __syncthreads();

    const int gw = blockIdx.x * 8 + (tid >> 5);
    if (gw > 256) return;
    const bool isC = (gw == 256);
    const int j = gw;

    float v[8], ex[2];
#pragma unroll
    for (int q = 0; q < 2; ++q)
        ex[q] = isC ? b1s[lane + 32*q] : w1[j*64 + lane + 32*q];
    v[0] = ex[0]; v[1] = ex[1];
    v[2]=v[3]=v[4]=v[5]=v[6]=v[7] = 0.f;

#pragma unroll
    for (int i = 1; i < 4; ++i) {
        const bool addEx = isC || (j >= 64 * i);
#pragma unroll 8
        for (int n = 0; n < 64; ++n) {
            float p = 0.f;
#pragma unroll
            for (int q = 0; q < 8; ++q)
                if (q < 2*i) p = fmaf(v[q], w1t[n*256 + lane + 32*q], p);
#pragma unroll
            for (int o = 16; o > 0; o >>= 1)
                p += __shfl_xor_sync(0xffffffffu, p, o);
            if (lane == (n & 31))
                v[2*i + (n >> 5)] = p + (addEx ? ex[n >> 5] : 0.f);
        }
    }

    if (isC) {
#pragma unroll
        for (int q = 0; q < 8; ++q) g_ceff[lane + 32*q] = v[q];
    } else {
#pragma unroll
        for (int q = 0; q < 8; ++q) g_Veff[j*256 + lane + 32*q] = v[q];
    }
}

// ---------------------------------------------------------------------------
// Weight prep: transpose + fp16-split + pre-swizzle all B tiles into g_Bbuf.
// ---------------------------------------------------------------------------
__global__ void wprep_kernel(const float* __restrict__ w2)
{
    const int b = blockIdx.x;
    const int tid = threadIdx.x;
    for (int it = 0; it < 16; ++it) {
        const int id = it * 256 + tid;
        const int n = id >> 6, k = id & 63;
        float val; int split;
        if (b < 32) {
            split = b >> 4; const int rem = b & 15;
            const int kc = rem >> 2, nt = rem & 3;
            val = g_Veff[(kc*64 + k)*256 + nt*64 + n];
        } else if (b < 104) {
            const int e = b - 32; split = e / 36; const int r = e % 36;
            const int t = r >> 2, kc = r & 3;
            val = w2[(size_t)t*16384 + (size_t)(kc*64 + k)*64 + n];
        } else {
            const int e = b - 104; const int j = e / 18; const int r = e % 18;
            split = r / 9; const int t = r % 9;
            val = w2[(size_t)t*16384 + (size_t)(j*64 + k)*64 + n];
        }
        const __half h = __float2half_rn(val);
        const __half l = __float2half_rn(val - __half2float(h));
        *reinterpret_cast<__half*>(
            reinterpret_cast<char*>(g_Bbuf) + (size_t)b*8192 + SW128(n*128 + k*2))
            = (split == 0) ? h : l;
    }
}

// ===========================================================================
// PHASE 1: Y1 = relu(x @ Veff + ceff)   (1x1 conv, K=256, grid 512 x 4)
// xcvt fused; A single fp16, B hi+lo (2-term kept for accuracy headroom).
// R13/14 configuration (412us best) — do not touch.
// ===========================================================================
#define SMEM1 98304
__device__ __forceinline__ uint32_t o1A(int buf) {
    return (uint32_t)buf*49152u;
}
__device__ __forceinline__ uint32_t o1B(int buf, int split) {
    return (uint32_t)buf*49152u + 32768u + (uint32_t)split*8192u;
}

__global__ void __launch_bounds__(256, 2)
mma_p1(const float* __restrict__ X,
       const float* __restrict__ bias)
{
    extern __shared__ char smem[];
    const uint32_t sb = s2u(smem);
    const int tid = threadIdx.x;
    const int lane = tid & 31;
    const int wid = tid >> 5;
    const int pxBase = blockIdx.x * 128;
    const int nt0 = blockIdx.y;
    const int n0 = nt0 * 64;
    const int wpx = (wid >> 1) * 32;
    const int wn  = (wid & 1) * 32;

    float c[2][4][4];
#pragma unroll
    for (int mt = 0; mt < 2; ++mt)
#pragma unroll
        for (int nt = 0; nt < 4; ++nt)
#pragma unroll
            for (int e = 0; e < 4; ++e) c[mt][nt][e] = 0.f;

    float4 xr[4][2];
    auto ldgA = [&](int cidx) {
#pragma unroll
        for (int it = 0; it < 4; ++it) {
            const int id = it * 256 + tid;
            const int r = id >> 3, u = id & 7;
            const long off = (long)(pxBase + r) * 256 + cidx*64 + u*8;
            xr[it][0] = *reinterpret_cast<const float4*>(X + off);
            xr[it][1] = *reinterpret_cast<const float4*>(X + off + 4);
        }
    };
    auto stsA = [&](int buf) {
#pragma unroll
        for (int it = 0; it < 4; ++it) {
            const int id = it * 256 + tid;
            const int r = id >> 3, u = id & 7;
            uint4 v;
            v.x = packh2(xr[it][0].x, xr[it][0].y);
            v.y = packh2(xr[it][0].z, xr[it][0].w);
            v.z = packh2(xr[it][1].x, xr[it][1].y);
            v.w = packh2(xr[it][1].z, xr[it][1].w);
            *reinterpret_cast<uint4*>(smem + o1A(buf) + SW128(r*128 + u*16)) = v;
        }
    };
    auto stageB = [&](int cidx, int buf) {
        const __half* bsH = g_Bbuf + (size_t)(cidx*4 + nt0) * 4096;
        const __half* bsL = g_Bbuf + (size_t)(16 + cidx*4 + nt0) * 4096;
#pragma unroll
        for (int it = 0; it < 2; ++it) {
            const int id = it * 256 + tid;
            cpa16(sb + o1B(buf,0) + id*16, bsH + id*8, true);
            cpa16(sb + o1B(buf,1) + id*16, bsL + id*8, true);
        }
        cpa_commit();
    };

    ldgA(0);
    stageB(0, 0);
    stsA(0);

#pragma unroll 1
    for (int cc = 0; cc < 4; ++cc) {
        if (cc + 1 < 4) {
            ldgA(cc + 1);
            stageB(cc + 1, (cc + 1) & 1);
            cpa_wait<1>();
        } else {
            cpa_wait<0>();
        }
        __syncthreads();

        const int buf = cc & 1;
        const uint32_t aBa = sb + o1A(buf);
        const uint32_t bHi = sb + o1B(buf,0), bLo = sb + o1B(buf,1);

#pragma unroll
        for (int ks = 0; ks < 4; ++ks) {
            uint32_t ah[2][4], bh[4][2], bl[4][2];
            {
                const int arow = wpx + ((lane >> 3) & 1) * 8 + (lane & 7);
                const int ak   = ks * 16 + (lane >> 4) * 8;
#pragma unroll
                for (int mt = 0; mt < 2; ++mt) {
                    const uint32_t asw = SW128((arow + mt*16) * 128 + ak * 2);
                    ldsm4(ah[mt], aBa + asw);
                }
            }
            {
                const int m = lane >> 3, r = lane & 7;
#pragma unroll
                for (int np = 0; np < 2; ++np) {
                    const int brow = wn + np*16 + (m >> 1) * 8 + r;
                    const int bk   = ks * 16 + (m & 1) * 8;
                    const uint32_t bsw = SW128(brow * 128 + bk * 2);
                    uint32_t rg[4];
                    ldsm4(rg, bHi + bsw);
                    bh[np*2+0][0] = rg[0]; bh[np*2+0][1] = rg[1];
                    bh[np*2+1][0] = rg[2]; bh[np*2+1][1] = rg[3];
                    ldsm4(rg, bLo + bsw);
                    bl[np*2+0][0] = rg[0]; bl[np*2+0][1] = rg[1];
                    bl[np*2+1][0] = rg[2]; bl[np*2+1][1] = rg[3];
                }
            }
#pragma unroll
            for (int mt = 0; mt < 2; ++mt)
#pragma unroll
                for (int nt = 0; nt < 4; ++nt) {
                    mma_f16(c[mt][nt], ah[mt], bh[nt]);
                    mma_f16(c[mt][nt], ah[mt], bl[nt]);
                }
        }
        if (cc + 1 < 4) stsA((cc + 1) & 1);
        __syncthreads();
    }

    const int g = lane >> 2, tq = lane & 3;
#pragma unroll
    for (int mt = 0; mt < 2; ++mt)
#pragma unroll
        for (int rh = 0; rh < 2; ++rh) {
            const size_t px = (size_t)pxBase + wpx + mt*16 + rh*8 + g;
#pragma unroll
            for (int nt = 0; nt < 4; ++nt) {
                const int ch = wn + nt*8 + tq*2;
                const float r0 = fmaxf(c[mt][nt][rh*2+0] + bias[n0+ch],   0.f);
                const float r1 = fmaxf(c[mt][nt][rh*2+1] + bias[n0+ch+1], 0.f);
                *reinterpret_cast<__half2*>(&g_Y1h[px*256 + n0 + ch]) =
                    __floats2half2_rn(r0, r1);
            }
        }
}

// ===========================================================================
// PHASE 2: 3x3 conv, CIN=256, HALO staging, flat 36-iter pipeline.
// NEW: SINGLE-TERM fp16 (weights hi only) — 1 MMA per tile per ks.
// smem: A halo double-buffered [0,67584) B hi double-buffered [67584+buf*8192)
// 83968 bytes -> 2 CTAs/SM.
// ===========================================================================
#define SMEM3 83968
#define A3BUF 33792u
__device__ __forceinline__ uint32_t o3B(int buf) {
    return 67584u + (uint32_t)buf*8192u;
}

__global__ void __launch_bounds__(256)
mma_p2(const __half* __restrict__ A,
       const float* __restrict__ bias,
       __half* __restrict__ DOut)
{
    extern __shared__ char smem[];
    const uint32_t sb = s2u(smem);
    const int tid = threadIdx.x;
    const int lane = tid & 31;
    const int wid = tid >> 5;
    const int pxBase = blockIdx.x * 128;
    const int y0 = (pxBase >> 6) & 63;
    const int img = pxBase >> 12;
    const int wpx = (wid >> 1) * 32;
    const int wn  = (wid & 1) * 32;

    float c[2][4][4];
#pragma unroll
    for (int mt = 0; mt < 2; ++mt)
#pragma unroll
        for (int nt = 0; nt < 4; ++nt)
#pragma unroll
            for (int e = 0; e < 4; ++e) c[mt][nt][e] = 0.f;

    auto stageA = [&](int kc, int abuf) {
#pragma unroll 1
        for (int it = 0; it < 9; ++it) {
            const int id = it * 256 + tid;
            if (id < 2112) {
                const int r = id >> 3, u = id & 7;
                const int row = r / 66;
                const int xt  = r - row * 66;
                const int y = y0 - 1 + row;
                const int x = xt - 1;
                const bool valid = ((unsigned)y < 64u) && ((unsigned)x < 64u);
                const long off = valid
                    ? ((long)(img*4096 + y*64 + x) * 256 + kc*64 + u*8) : 0L;
                cpa16(sb + abuf*A3BUF + SW128(r*128 + u*16), A + off, valid);
            }
        }
    };

    auto stageB = [&](int q, int buf) {
        const int kc = q / 9, t = q - kc * 9;
        const __half* bsH = g_Bbuf + (size_t)(32 + t*4 + kc) * 4096;
#pragma unroll
        for (int it = 0; it < 2; ++it) {
            const int id = it * 256 + tid;
            cpa16(sb + o3B(buf) + id*16, bsH + id*8, true);
        }
    };

    stageA(0, 0);
    stageB(0, 0);
    cpa_commit();

#pragma unroll 1
    for (int q = 0; q < 36; ++q) {
        const int kc = q / 9, t = q - kc * 9;
        if (q + 1 < 36) {
            stageB(q + 1, (q + 1) & 1);
            if (t == 0 && kc + 1 < 4) stageA(kc + 1, (kc + 1) & 1);
            cpa_commit();
            cpa_wait<1>();
        } else {
            cpa_wait<0>();
        }
        __syncthreads();

        const int dy = t / 3 - 1;
        const int dx = t % 3 - 1;
        const uint32_t aBa = sb + (kc & 1) * A3BUF;
        const uint32_t bHi = sb + o3B(q & 1);

#pragma unroll
        for (int ks = 0; ks < 4; ++ks) {
            uint32_t ah[2][4], bh[4][2];
            {
                const int arow = wpx + ((lane >> 3) & 1) * 8 + (lane & 7);
                const int ak   = ks * 16 + (lane >> 4) * 8;
#pragma unroll
                for (int mt = 0; mt < 2; ++mt) {
                    const int ar = arow + mt*16;
                    const int tpx = ((ar >> 6) + dy + 1) * 66 + (ar & 63) + dx + 1;
                    ldsm4(ah[mt], aBa + SW128(tpx * 128 + ak * 2));
                }
            }
            {
                const int m = lane >> 3, r = lane & 7;
#pragma unroll
                for (int np = 0; np < 2; ++np) {
                    const int brow = wn + np*16 + (m >> 1) * 8 + r;
                    const int bk   = ks * 16 + (m & 1) * 8;
                    uint32_t rg[4];
                    ldsm4(rg, bHi + SW128(brow * 128 + bk * 2));
                    bh[np*2+0][0] = rg[0]; bh[np*2+0][1] = rg[1];
                    bh[np*2+1][0] = rg[2]; bh[np*2+1][1] = rg[3];
                }
            }
#pragma unroll
            for (int mt = 0; mt < 2; ++mt)
#pragma unroll
                for (int nt = 0; nt < 4; ++nt)
                    mma_f16(c[mt][nt], ah[mt], bh[nt]);
        }
        __syncthreads();
    }

    const int g = lane >> 2, tq = lane & 3;
#pragma unroll
    for (int mt = 0; mt < 2; ++mt) {
#pragma unroll
        for (int rh = 0; rh < 2; ++rh) {
            const size_t px = (size_t)pxBase + wpx + mt*16 + rh*8 + g;
#pragma unroll
            for (int nt = 0; nt < 4; ++nt) {
                const int ch = wn + nt*8 + tq*2;
                const float r0 = c[mt][nt][rh*2 + 0] + bias[ch];
                const float r1 = c[mt][nt][rh*2 + 1] + bias[ch+1];
                float2 rr; rr.x = r0; rr.y = r1;
                *reinterpret_cast<float2*>(&g_base[px*64 + ch]) = rr;
                *reinterpret_cast<float2*>(&g_Y2[px*256 + ch])  = rr;
                const __half2 y = *reinterpret_cast<const __half2*>(&g_Y1h[px*256 + ch]);
                const float dd0 = r0 - __half2float(y.x);
                const float dd1 = r1 - __half2float(y.y);
                *reinterpret_cast<__half2*>(&DOut[px*64 + ch]) =
                    __floats2half2_rn(dd0, dd1);
            }
        }
    }
}

// ===========================================================================
// CORRECTIONS: 3x3 conv, CIN=64, single-term fp16 (R14 configuration).
// ===========================================================================
#define SMEMC 50176
__device__ __forceinline__ uint32_t oCB(int buf) {
    return 33792u + (uint32_t)buf*8192u;
}

__global__ void __launch_bounds__(256)
mma_corr(const __half* __restrict__ A,
         __half* __restrict__ DOut,
         int jblk, int accumPrev)
{
    extern __shared__ char smem[];
    const uint32_t sb = s2u(smem);
    const int tid = threadIdx.x;
    const int lane = tid & 31;
    const int wid = tid >> 5;
    const int pxBase = blockIdx.x * 128;
    const int y0 = (pxBase >> 6) & 63;
    const int img = pxBase >> 12;
    const int wpx = (wid >> 1) * 32;
    const int wn  = (wid & 1) * 32;

    float c[2][4][4];
#pragma unroll
    for (int mt = 0; mt < 2; ++mt)
#pragma unroll
        for (int nt = 0; nt < 4; ++nt)
#pragma unroll
            for (int e = 0; e < 4; ++e) c[mt][nt][e] = 0.f;

#pragma unroll 1
    for (int it = 0; it < 9; ++it) {
        const int id = it * 256 + tid;
        if (id < 2112) {
            const int r = id >> 3, u = id & 7;
            const int row = r / 66;
            const int xt  = r - row * 66;
            const int y = y0 - 1 + row;
            const int x = xt - 1;
            const bool valid = ((unsigned)y < 64u) && ((unsigned)x < 64u);
            const long off = valid
                ? ((long)(img*4096 + y*64 + x) * 64 + u*8) : 0L;
            cpa16(sb + SW128(r*128 + u*16), A + off, valid);
        }
    }

    auto stageB = [&](int t, int buf) {
        const __half* bsH = g_Bbuf + (size_t)(104 + jblk*18 + t) * 4096;
#pragma unroll
        for (int it = 0; it < 2; ++it) {
            const int id = it * 256 + tid;
            cpa16(sb + oCB(buf) + id*16, bsH + id*8, true);
        }
    };

    stageB(0, 0);
    cpa_commit();
#pragma unroll 1
    for (int t = 0; t < 9; ++t) {
        if (t < 8) { stageB(t + 1, (t + 1) & 1); cpa_commit(); cpa_wait<1>(); }
        else       { cpa_wait<0>(); }
        __syncthreads();

        const int dy = t / 3 - 1;
        const int dx = t % 3 - 1;
        const uint32_t bHi = sb + oCB(t & 1);

#pragma unroll
        for (int ks = 0; ks < 4; ++ks) {
            uint32_t ah[2][4], bh[4][2];
            {
                const int arow = wpx + ((lane >> 3) & 1) * 8 + (lane & 7);
                const int ak   = ks * 16 + (lane >> 4) * 8;
#pragma unroll
                for (int mt = 0; mt < 2; ++mt) {
                    const int ar = arow + mt*16;
                    const int tpx = ((ar >> 6) + dy + 1) * 66 + (ar & 63) + dx + 1;
                    ldsm4(ah[mt], sb + SW128(tpx * 128 + ak * 2));
                }
            }
            {
                const int m = lane >> 3, r = lane & 7;
#pragma unroll
                for (int np = 0; np < 2; ++np) {
                    const int brow = wn + np*16 + (m >> 1) * 8 + r;
                    const int bk   = ks * 16 + (m & 1) * 8;
                    uint32_t rg[4];
                    ldsm4(rg, bHi + SW128(brow * 128 + bk * 2));
                    bh[np*2+0][0] = rg[0]; bh[np*2+0][1] = rg[1];
                    bh[np*2+1][0] = rg[2]; bh[np*2+1][1] = rg[3];
                }
            }
#pragma unroll
            for (int mt = 0; mt < 2; ++mt)
#pragma unroll
                for (int nt = 0; nt < 4; ++nt)
                    mma_f16(c[mt][nt], ah[mt], bh[nt]);
        }
        __syncthreads();
    }

    const int g = lane >> 2, tq = lane & 3;
#pragma unroll
    for (int mt = 0; mt < 2; ++mt) {
#pragma unroll
        for (int rh = 0; rh < 2; ++rh) {
            const size_t px = (size_t)pxBase + wpx + mt*16 + rh*8 + g;
#pragma unroll
            for (int nt = 0; nt < 4; ++nt) {
                const int ch = wn + nt*8 + tq*2;
                float r0 = c[mt][nt][rh*2 + 0];
                float r1 = c[mt][nt][rh*2 + 1];
                if (accumPrev) {
                    const float2 a = *reinterpret_cast<const float2*>(&g_Acc[px*64 + ch]);
                    r0 += a.x; r1 += a.y;
                }
                float2 rr; rr.x = r0; rr.y = r1;
                *reinterpret_cast<float2*>(&g_Acc[px*64 + ch]) = rr;
                const float2 b = *reinterpret_cast<const float2*>(&g_base[px*64 + ch]);
                const float z0 = b.x + r0, z1 = b.y + r1;
                float2 zz; zz.x = z0; zz.y = z1;
                *reinterpret_cast<float2*>(&g_Y2[px*256 + (jblk+1)*64 + ch]) = zz;
                if (jblk < 2) {
                    const __half2 y = *reinterpret_cast<const __half2*>(
                        &g_Y1h[px*256 + (jblk+1)*64 + ch]);
                    const float dd0 = z0 - __half2float(y.x);
                    const float dd1 = z1 - __half2float(y.y);
                    *reinterpret_cast<__half2*>(&DOut[px*64 + ch]) =
                        __floats2half2_rn(dd0, dd1);
                }
            }
        }
    }
}

// ---------------------------------------------------------------------------
// Step3: per-pixel scalar recurrence (replaces 256 sequential 1x1 convs)
// ---------------------------------------------------------------------------
__global__ void __launch_bounds__(256)
step3_kernel(const float* __restrict__ x,
             const float* __restrict__ w3,
             const float* __restrict__ b3,
             float* __restrict__ out)
{
    __shared__ float sA[32][257];
    __shared__ float sw[256];
    const int tid = threadIdx.x;
    const size_t pBase = (size_t)blockIdx.x * 32;
    sw[tid] = w3[tid];

#pragma unroll
    for (int it = 0; it < 8; ++it) {
        const int g = it * 256 + tid;
        const int px = g >> 6;
        const int c = (g & 63) * 4;
        const float4 v = *reinterpret_cast<const float4*>(g_Y2 + (pBase + px)*256 + c);
        sA[px][c + 0] = fmaxf(v.x, 0.f);
        sA[px][c + 1] = fmaxf(v.y, 0.f);
        sA[px][c + 2] = fmaxf(v.z, 0.f);
        sA[px][c + 3] = fmaxf(v.w, 0.f);
    }
    __syncthreads();

    if (tid < 32) {
        float dot = 0.f;
#pragma unroll 8
        for (int c = 0; c < 256; ++c) dot = fmaf(sA[tid][c], sw[c], dot);
        const float bb = b3[0];
#pragma unroll 1
        for (int i = 0; i < 256; ++i) {
            const float a = sA[tid][i];
            const float z = dot + bb;
            sA[tid][i] = z;
            dot = fmaf(z - a, sw[i], dot);
        }
    }
    __syncthreads();

#pragma unroll
    for (int it = 0; it < 8; ++it) {
        const int g = it * 256 + tid;
        const int px = g >> 6;
        const int c = (g & 63) * 4;
        const float4 xv = *reinterpret_cast<const float4*>(x + (pBase + px)*256 + c);
        float4 r;
        r.x = sA[px][c + 0] + xv.x;
        r.y = sA[px][c + 1] + xv.y;
        r.z = sA[px][c + 2] + xv.z;
        r.w = sA[px][c + 3] + xv.w;
        *reinterpret_cast<float4*>(out + (pBase + px)*256 + c) = r;
    }
}

// ---------------------------------------------------------------------------
// Launch
// ---------------------------------------------------------------------------
extern "C" void kernel_launch(void* const* d_in, const int* in_sizes, int n_in,
                              void* d_out, int out_size)
{
    const float* x  = (const float*)d_in[0];
    const float* w1 = (const float*)d_in[1];
    const float* b1 = (const float*)d_in[2];
    const float* w2 = (const float*)d_in[3];
    const float* b2 = (const float*)d_in[4];
    const float* w3 = (const float*)d_in[5];
    const float* b3 = (const float*)d_in[6];
    float* out = (float*)d_out;

    __half *Y1h, *Dh0, *Dh1;
    float *ceff;
    cudaGetSymbolAddress((void**)&Y1h,  g_Y1h);
    cudaGetSymbolAddress((void**)&Dh0,  g_Dh0);
    cudaGetSymbolAddress((void**)&Dh1,  g_Dh1);
    cudaGetSymbolAddress((void**)&ceff, g_ceff);

    cudaFuncSetAttribute(compose_kernel,
                         cudaFuncAttributeMaxDynamicSharedMemorySize, COMPOSE_SMEM);
    cudaFuncSetAttribute(mma_p1,
                         cudaFuncAttributeMaxDynamicSharedMemorySize, SMEM1);
    cudaFuncSetAttribute(mma_p2,
                         cudaFuncAttributeMaxDynamicSharedMemorySize, SMEM3);
    cudaFuncSetAttribute(mma_corr,
                         cudaFuncAttributeMaxDynamicSharedMemorySize, SMEMC);

    // Phase 0: compose step1 weights; prep B tiles (xcvt fused into p1)
    compose_kernel<<<33, 256, COMPOSE_SMEM>>>(w1, b1);
    wprep_kernel<<<158, 256>>>(w2);

    // Phase 1: Y1 = relu(x @ Veff + ceff)   (converts x->fp16 inline)
    mma_p1<<<dim3(512, 4), 256, SMEM1>>>(x, ceff);

    // Phase 2: base = conv3x3(Y1, W2) + b2; Y2 blk0; D0
    mma_p2<<<512, 256, SMEM3>>>(Y1h, b2, Dh0);

    // Corrections: Z_{j+1} = base + sum_{m<=j} conv3x3(D_m, W2_blk_m)
    for (int j = 0; j < 3; ++j) {
        const __half* Ain = (j & 1) ? Dh1 : Dh0;
        __half*       Dn  = (j & 1) ? Dh0 : Dh1;
        mma_corr<<<512, 256, SMEMC>>>(Ain, Dn, j, (j > 0) ? 1 : 0);
    }

    // Phase 3: per-pixel recurrence + residual
    step3_kernel<<<2048, 256>>>(x, w3, b3, out);
}

// round 16
// speedup vs baseline: 1.1612x; 1.0413x over previous
#include <cuda_runtime.h>
#include <cuda_fp16.h>
#include <cstdint>
#include <cstddef>

#define PTOT (16*64*64)   // 65536 pixels, NHWC (C fastest)

// ---------------------------------------------------------------------------
// Device globals (no cudaMalloc allowed)
// ---------------------------------------------------------------------------
__device__ float g_Veff[256*256];
__device__ float g_ceff[256];
__device__ __half g_Y1h[(size_t)PTOT*256];
__device__ float g_Y2[(size_t)PTOT*256];
__device__ float g_base[(size_t)PTOT*64];
__device__ float g_Acc[(size_t)PTOT*64];
__device__ __half g_Dh0[(size_t)PTOT*64];
__device__ __half g_Dh1[(size_t)PTOT*64];
__device__ __half g_Bbuf[158*4096];           // fp16 hi/lo weight tiles

// ---------------------------------------------------------------------------
// PTX helpers (sm_80-compatible only; ptxas here targets plain sm_103)
// ---------------------------------------------------------------------------
__device__ __forceinline__ uint32_t s2u(const void* p) {
    uint32_t a;
    asm("{ .reg .u64 t; cvta.to.shared.u64 t, %1; cvt.u32.u64 %0, t; }"
        : "=r"(a) : "l"(p));
    return a;
}
#define SW128(o) ((uint32_t)(o) ^ (((uint32_t)(o) >> 3) & 0x70u))

__device__ __forceinline__ void cpa16(uint32_t dst, const void* src, bool valid) {
    asm volatile("cp.async.ca.shared.global [%0], [%1], 16, %2;"
                 :: "r"(dst), "l"(src), "r"(valid ? 16 : 0) : "memory");
}
__device__ __forceinline__ void cpa_commit() {
    asm volatile("cp.async.commit_group;" ::: "memory");
}
template<int N> __device__ __forceinline__ void cpa_wait() {
    asm volatile("cp.async.wait_group %0;" :: "n"(N) : "memory");
}

__device__ __forceinline__ void ldsm4(uint32_t* r, uint32_t addr) {
    asm volatile("ldmatrix.sync.aligned.m8n8.x4.shared.b16 {%0,%1,%2,%3}, [%4];"
                 : "=r"(r[0]), "=r"(r[1]), "=r"(r[2]), "=r"(r[3]) : "r"(addr));
}
__device__ __forceinline__ void mma_f16(float* c, const uint32_t* a, const uint32_t* b) {
    asm volatile(
        "mma.sync.aligned.m16n8k16.row.col.f32.f16.f16.f32 "
        "{%0,%1,%2,%3}, {%4,%5,%6,%7}, {%8,%9}, {%0,%1,%2,%3};"
        : "+f"(c[0]), "+f"(c[1]), "+f"(c[2]), "+f"(c[3])
        : "r"(a[0]), "r"(a[1]), "r"(a[2]), "r"(a[3]), "r"(b[0]), "r"(b[1]));
}
__device__ __forceinline__ uint32_t packh2(float a, float b) {
    __half2 h = __floats2half2_rn(a, b);
    return *reinterpret_cast<uint32_t*>(&h);
}

// ---------------------------------------------------------------------------
// Step1 composition in ONE kernel. One warp per row; state in registers.
// ---------------------------------------------------------------------------
#define COMPOSE_SMEM (64*256*4 + 64*4)
__global__ void __launch_bounds__(256)
compose_kernel(const float* __restrict__ w1, const float* __restrict__ b1)
{
    extern __shared__ float sh[];
    float* w1t = sh;
    float* b1s = sh + 64*256;
    const int tid = threadIdx.x;
    const int lane = tid & 31;

#pragma unroll
    for (int it = 0; it < 64; ++it) {
        const int id = it * 256 + tid;
        const int m = id >> 6, n = id & 63;
        w1t[n*256 + m] = w1[id];
    }
    if (tid < 64) b1s[tid] = b1[tid];
    __syncthreads();

    const int gw = blockIdx.x * 8 + (tid >> 5);
    if (gw > 256) return;
    const bool isC = (gw == 256);
    const int j = gw;

    float v[8], ex[2];
#pragma unroll
    for (int q = 0; q < 2; ++q)
        ex[q] = isC ? b1s[lane + 32*q] : w1[j*64 + lane + 32*q];
    v[0] = ex[0]; v[1] = ex[1];
    v[2]=v[3]=v[4]=v[5]=v[6]=v[7] = 0.f;

#pragma unroll
    for (int i = 1; i < 4; ++i) {
        const bool addEx = isC || (j >= 64 * i);
#pragma unroll 8
        for (int n = 0; n < 64; ++n) {
            float p = 0.f;
#pragma unroll
            for (int q = 0; q < 8; ++q)
                if (q < 2*i) p = fmaf(v[q], w1t[n*256 + lane + 32*q], p);
#pragma unroll
            for (int o = 16; o > 0; o >>= 1)
                p += __shfl_xor_sync(0xffffffffu, p, o);
            if (lane == (n & 31))
                v[2*i + (n >> 5)] = p + (addEx ? ex[n >> 5] : 0.f);
        }
    }

    if (isC) {
#pragma unroll
        for (int q = 0; q < 8; ++q) g_ceff[lane + 32*q] = v[q];
    } else {
#pragma unroll
        for (int q = 0; q < 8; ++q) g_Veff[j*256 + lane + 32*q] = v[q];
    }
}

// ---------------------------------------------------------------------------
// Weight prep: transpose + fp16-split + pre-swizzle all B tiles into g_Bbuf.
// (lo tiles still produced; only hi tiles are consumed now)
// ---------------------------------------------------------------------------
__global__ void wprep_kernel(const float* __restrict__ w2)
{
    const int b = blockIdx.x;
    const int tid = threadIdx.x;
    for (int it = 0; it < 16; ++it) {
        const int id = it * 256 + tid;
        const int n = id >> 6, k = id & 63;
        float val; int split;
        if (b < 32) {
            split = b >> 4; const int rem = b & 15;
            const int kc = rem >> 2, nt = rem & 3;
            val = g_Veff[(kc*64 + k)*256 + nt*64 + n];
        } else if (b < 104) {
            const int e = b - 32; split = e / 36; const int r = e % 36;
            const int t = r >> 2, kc = r & 3;
            val = w2[(size_t)t*16384 + (size_t)(kc*64 + k)*64 + n];
        } else {
            const int e = b - 104; const int j = e / 18; const int r = e % 18;
            split = r / 9; const int t = r % 9;
            val = w2[(size_t)t*16384 + (size_t)(j*64 + k)*64 + n];
        }
        const __half h = __float2half_rn(val);
        const __half l = __float2half_rn(val - __half2float(h));
        *reinterpret_cast<__half*>(
            reinterpret_cast<char*>(g_Bbuf) + (size_t)b*8192 + SW128(n*128 + k*2))
            = (split == 0) ? h : l;
    }
}

// ===========================================================================
// PHASE 1: Y1 = relu(x @ Veff + ceff)   (1x1 conv, K=256, grid 512 x 4)
// xcvt fused; A single fp16, B hi ONLY (single-term, like p2/corr).
// smem: A [buf*40960, +32768) B [buf*40960+32768, +8192)   = 81920 total.
// ===========================================================================
#define SMEM1 81920
__device__ __forceinline__ uint32_t o1A(int buf) {
    return (uint32_t)buf*40960u;
}
__device__ __forceinline__ uint32_t o1B(int buf) {
    return (uint32_t)buf*40960u + 32768u;
}

__global__ void __launch_bounds__(256, 2)
mma_p1(const float* __restrict__ X,
       const float* __restrict__ bias)
{
    extern __shared__ char smem[];
    const uint32_t sb = s2u(smem);
    const int tid = threadIdx.x;
    const int lane = tid & 31;
    const int wid = tid >> 5;
    const int pxBase = blockIdx.x * 128;
    const int nt0 = blockIdx.y;
    const int n0 = nt0 * 64;
    const int wpx = (wid >> 1) * 32;
    const int wn  = (wid & 1) * 32;

    float c[2][4][4];
#pragma unroll
    for (int mt = 0; mt < 2; ++mt)
#pragma unroll
        for (int nt = 0; nt < 4; ++nt)
#pragma unroll
            for (int e = 0; e < 4; ++e) c[mt][nt][e] = 0.f;

    float4 xr[4][2];
    auto ldgA = [&](int cidx) {
#pragma unroll
        for (int it = 0; it < 4; ++it) {
            const int id = it * 256 + tid;
            const int r = id >> 3, u = id & 7;
            const long off = (long)(pxBase + r) * 256 + cidx*64 + u*8;
            xr[it][0] = *reinterpret_cast<const float4*>(X + off);
            xr[it][1] = *reinterpret_cast<const float4*>(X + off + 4);
        }
    };
    auto stsA = [&](int buf) {
#pragma unroll
        for (int it = 0; it < 4; ++it) {
            const int id = it * 256 + tid;
            const int r = id >> 3, u = id & 7;
            uint4 v;
            v.x = packh2(xr[it][0].x, xr[it][0].y);
            v.y = packh2(xr[it][0].z, xr[it][0].w);
            v.z = packh2(xr[it][1].x, xr[it][1].y);
            v.w = packh2(xr[it][1].z, xr[it][1].w);
            *reinterpret_cast<uint4*>(smem + o1A(buf) + SW128(r*128 + u*16)) = v;
        }
    };
    auto stageB = [&](int cidx, int buf) {
        const __half* bsH = g_Bbuf + (size_t)(cidx*4 + nt0) * 4096;
#pragma unroll
        for (int it = 0; it < 2; ++it) {
            const int id = it * 256 + tid;
            cpa16(sb + o1B(buf) + id*16, bsH + id*8, true);
        }
        cpa_commit();
    };

    ldgA(0);
    stageB(0, 0);
    stsA(0);

#pragma unroll 1
    for (int cc = 0; cc < 4; ++cc) {
        if (cc + 1 < 4) {
            ldgA(cc + 1);
            stageB(cc + 1, (cc + 1) & 1);
            cpa_wait<1>();
        } else {
            cpa_wait<0>();
        }
        __syncthreads();

        const int buf = cc & 1;
        const uint32_t aBa = sb + o1A(buf);
        const uint32_t bHi = sb + o1B(buf);

#pragma unroll
        for (int ks = 0; ks < 4; ++ks) {
            uint32_t ah[2][4], bh[4][2];
            {
                const int arow = wpx + ((lane >> 3) & 1) * 8 + (lane & 7);
                const int ak   = ks * 16 + (lane >> 4) * 8;
#pragma unroll
                for (int mt = 0; mt < 2; ++mt) {
                    const uint32_t asw = SW128((arow + mt*16) * 128 + ak * 2);
                    ldsm4(ah[mt], aBa + asw);
                }
            }
            {
                const int m = lane >> 3, r = lane & 7;
#pragma unroll
                for (int np = 0; np < 2; ++np) {
                    const int brow = wn + np*16 + (m >> 1) * 8 + r;
                    const int bk   = ks * 16 + (m & 1) * 8;
                    uint32_t rg[4];
                    ldsm4(rg, bHi + SW128(brow * 128 + bk * 2));
                    bh[np*2+0][0] = rg[0]; bh[np*2+0][1] = rg[1];
                    bh[np*2+1][0] = rg[2]; bh[np*2+1][1] = rg[3];
                }
            }
#pragma unroll
            for (int mt = 0; mt < 2; ++mt)
#pragma unroll
                for (int nt = 0; nt < 4; ++nt)
                    mma_f16(c[mt][nt], ah[mt], bh[nt]);
        }
        if (cc + 1 < 4) stsA((cc + 1) & 1);
        __syncthreads();
    }

    const int g = lane >> 2, tq = lane & 3;
#pragma unroll
    for (int mt = 0; mt < 2; ++mt)
#pragma unroll
        for (int rh = 0; rh < 2; ++rh) {
            const size_t px = (size_t)pxBase + wpx + mt*16 + rh*8 + g;
#pragma unroll
            for (int nt = 0; nt < 4; ++nt) {
                const int ch = wn + nt*8 + tq*2;
                const float r0 = fmaxf(c[mt][nt][rh*2+0] + bias[n0+ch],   0.f);
                const float r1 = fmaxf(c[mt][nt][rh*2+1] + bias[n0+ch+1], 0.f);
                *reinterpret_cast<__half2*>(&g_Y1h[px*256 + n0 + ch]) =
                    __floats2half2_rn(r0, r1);
            }
        }
}

// ===========================================================================
// PHASE 2: 3x3 conv, CIN=256, HALO staging, flat 36-iter pipeline,
// single-term fp16 (R15 configuration — do not touch).
// ===========================================================================
#define SMEM3 83968
#define A3BUF 33792u
__device__ __forceinline__ uint32_t o3B(int buf) {
    return 67584u + (uint32_t)buf*8192u;
}

__global__ void __launch_bounds__(256)
mma_p2(const __half* __restrict__ A,
       const float* __restrict__ bias,
       __half* __restrict__ DOut)
{
    extern __shared__ char smem[];
    const uint32_t sb = s2u(smem);
    const int tid = threadIdx.x;
    const int lane = tid & 31;
    const int wid = tid >> 5;
    const int pxBase = blockIdx.x * 128;
    const int y0 = (pxBase >> 6) & 63;
    const int img = pxBase >> 12;
    const int wpx = (wid >> 1) * 32;
    const int wn  = (wid & 1) * 32;

    float c[2][4][4];
#pragma unroll
    for (int mt = 0; mt < 2; ++mt)
#pragma unroll
        for (int nt = 0; nt < 4; ++nt)
#pragma unroll
            for (int e = 0; e < 4; ++e) c[mt][nt][e] = 0.f;

    auto stageA = [&](int kc, int abuf) {
#pragma unroll 1
        for (int it = 0; it < 9; ++it) {
            const int id = it * 256 + tid;
            if (id < 2112) {
                const int r = id >> 3, u = id & 7;
                const int row = r / 66;
                const int xt  = r - row * 66;
                const int y = y0 - 1 + row;
                const int x = xt - 1;
                const bool valid = ((unsigned)y < 64u) && ((unsigned)x < 64u);
                const long off = valid
                    ? ((long)(img*4096 + y*64 + x) * 256 + kc*64 + u*8) : 0L;
                cpa16(sb + abuf*A3BUF + SW128(r*128 + u*16), A + off, valid);
            }
        }
    };

    auto stageB = [&](int q, int buf) {
        const int kc = q / 9, t = q - kc * 9;
        const __half* bsH = g_Bbuf + (size_t)(32 + t*4 + kc) * 4096;
#pragma unroll
        for (int it = 0; it < 2; ++it) {
            const int id = it * 256 + tid;
            cpa16(sb + o3B(buf) + id*16, bsH + id*8, true);
        }
    };

    stageA(0, 0);
    stageB(0, 0);
    cpa_commit();

#pragma unroll 1
    for (int q = 0; q < 36; ++q) {
        const int kc = q / 9, t = q - kc * 9;
        if (q + 1 < 36) {
            stageB(q + 1, (q + 1) & 1);
            if (t == 0 && kc + 1 < 4) stageA(kc + 1, (kc + 1) & 1);
            cpa_commit();
            cpa_wait<1>();
        } else {
            cpa_wait<0>();
        }
        __syncthreads();

        const int dy = t / 3 - 1;
        const int dx = t % 3 - 1;
        const uint32_t aBa = sb + (kc & 1) * A3BUF;
        const uint32_t bHi = sb + o3B(q & 1);

#pragma unroll
        for (int ks = 0; ks < 4; ++ks) {
            uint32_t ah[2][4], bh[4][2];
            {
                const int arow = wpx + ((lane >> 3) & 1) * 8 + (lane & 7);
                const int ak   = ks * 16 + (lane >> 4) * 8;
#pragma unroll
                for (int mt = 0; mt < 2; ++mt) {
                    const int ar = arow + mt*16;
                    const int tpx = ((ar >> 6) + dy + 1) * 66 + (ar & 63) + dx + 1;
                    ldsm4(ah[mt], aBa + SW128(tpx * 128 + ak * 2));
                }
            }
            {
                const int m = lane >> 3, r = lane & 7;
#pragma unroll
                for (int np = 0; np < 2; ++np) {
                    const int brow = wn + np*16 + (m >> 1) * 8 + r;
                    const int bk   = ks * 16 + (m & 1) * 8;
                    uint32_t rg[4];
                    ldsm4(rg, bHi + SW128(brow * 128 + bk * 2));
                    bh[np*2+0][0] = rg[0]; bh[np*2+0][1] = rg[1];
                    bh[np*2+1][0] = rg[2]; bh[np*2+1][1] = rg[3];
                }
            }
#pragma unroll
            for (int mt = 0; mt < 2; ++mt)
#pragma unroll
                for (int nt = 0; nt < 4; ++nt)
                    mma_f16(c[mt][nt], ah[mt], bh[nt]);
        }
        __syncthreads();
    }

    const int g = lane >> 2, tq = lane & 3;
#pragma unroll
    for (int mt = 0; mt < 2; ++mt) {
#pragma unroll
        for (int rh = 0; rh < 2; ++rh) {
            const size_t px = (size_t)pxBase + wpx + mt*16 + rh*8 + g;
#pragma unroll
            for (int nt = 0; nt < 4; ++nt) {
                const int ch = wn + nt*8 + tq*2;
                const float r0 = c[mt][nt][rh*2 + 0] + bias[ch];
                const float r1 = c[mt][nt][rh*2 + 1] + bias[ch+1];
                float2 rr; rr.x = r0; rr.y = r1;
                *reinterpret_cast<float2*>(&g_base[px*64 + ch]) = rr;
                *reinterpret_cast<float2*>(&g_Y2[px*256 + ch])  = rr;
                const __half2 y = *reinterpret_cast<const __half2*>(&g_Y1h[px*256 + ch]);
                const float dd0 = r0 - __half2float(y.x);
                const float dd1 = r1 - __half2float(y.y);
                *reinterpret_cast<__half2*>(&DOut[px*64 + ch]) =
                    __floats2half2_rn(dd0, dd1);
            }
        }
    }
}

// ===========================================================================
// CORRECTIONS: 3x3 conv, CIN=64, single-term fp16 (R14/15 configuration).
// ===========================================================================
#define SMEMC 50176
__device__ __forceinline__ uint32_t oCB(int buf) {
    return 33792u + (uint32_t)buf*8192u;
}

__global__ void __launch_bounds__(256)
mma_corr(const __half* __restrict__ A,
         __half* __restrict__ DOut,
         int jblk, int accumPrev)
{
    extern __shared__ char smem[];
    const uint32_t sb = s2u(smem);
    const int tid = threadIdx.x;
    const int lane = tid & 31;
    const int wid = tid >> 5;
    const int pxBase = blockIdx.x * 128;
    const int y0 = (pxBase >> 6) & 63;
    const int img = pxBase >> 12;
    const int wpx = (wid >> 1) * 32;
    const int wn  = (wid & 1) * 32;

    float c[2][4][4];
#pragma unroll
    for (int mt = 0; mt < 2; ++mt)
#pragma unroll
        for (int nt = 0; nt < 4; ++nt)
#pragma unroll
            for (int e = 0; e < 4; ++e) c[mt][nt][e] = 0.f;

#pragma unroll 1
    for (int it = 0; it < 9; ++it) {
        const int id = it * 256 + tid;
        if (id < 2112) {
            const int r = id >> 3, u = id & 7;
            const int row = r / 66;
            const int xt  = r - row * 66;
            const int y = y0 - 1 + row;
            const int x = xt - 1;
            const bool valid = ((unsigned)y < 64u) && ((unsigned)x < 64u);
            const long off = valid
                ? ((long)(img*4096 + y*64 + x) * 64 + u*8) : 0L;
            cpa16(sb + SW128(r*128 + u*16), A + off, valid);
        }
    }

    auto stageB = [&](int t, int buf) {
        const __half* bsH = g_Bbuf + (size_t)(104 + jblk*18 + t) * 4096;
#pragma unroll
        for (int it = 0; it < 2; ++it) {
            const int id = it * 256 + tid;
            cpa16(sb + oCB(buf) + id*16, bsH + id*8, true);
        }
    };

    stageB(0, 0);
    cpa_commit();
#pragma unroll 1
    for (int t = 0; t < 9; ++t) {
        if (t < 8) { stageB(t + 1, (t + 1) & 1); cpa_commit(); cpa_wait<1>(); }
        else       { cpa_wait<0>(); }
        __syncthreads();

        const int dy = t / 3 - 1;
        const int dx = t % 3 - 1;
        const uint32_t bHi = sb + oCB(t & 1);

#pragma unroll
        for (int ks = 0; ks < 4; ++ks) {
            uint32_t ah[2][4], bh[4][2];
            {
                const int arow = wpx + ((lane >> 3) & 1) * 8 + (lane & 7);
                const int ak   = ks * 16 + (lane >> 4) * 8;
#pragma unroll
                for (int mt = 0; mt < 2; ++mt) {
                    const int ar = arow + mt*16;
                    const int tpx = ((ar >> 6) + dy + 1) * 66 + (ar & 63) + dx + 1;
                    ldsm4(ah[mt], sb + SW128(tpx * 128 + ak * 2));
                }
            }
            {
                const int m = lane >> 3, r = lane & 7;
#pragma unroll
                for (int np = 0; np < 2; ++np) {
                    const int brow = wn + np*16 + (m >> 1) * 8 + r;
                    const int bk   = ks * 16 + (m & 1) * 8;
                    uint32_t rg[4];
                    ldsm4(rg, bHi + SW128(brow * 128 + bk * 2));
                    bh[np*2+0][0] = rg[0]; bh[np*2+0][1] = rg[1];
                    bh[np*2+1][0] = rg[2]; bh[np*2+1][1] = rg[3];
                }
            }
#pragma unroll
            for (int mt = 0; mt < 2; ++mt)
#pragma unroll
                for (int nt = 0; nt < 4; ++nt)
                    mma_f16(c[mt][nt], ah[mt], bh[nt]);
        }
        __syncthreads();
    }

    const int g = lane >> 2, tq = lane & 3;
#pragma unroll
    for (int mt = 0; mt < 2; ++mt) {
#pragma unroll
        for (int rh = 0; rh < 2; ++rh) {
            const size_t px = (size_t)pxBase + wpx + mt*16 + rh*8 + g;
#pragma unroll
            for (int nt = 0; nt < 4; ++nt) {
                const int ch = wn + nt*8 + tq*2;
                float r0 = c[mt][nt][rh*2 + 0];
                float r1 = c[mt][nt][rh*2 + 1];
                if (accumPrev) {
                    const float2 a = *reinterpret_cast<const float2*>(&g_Acc[px*64 + ch]);
                    r0 += a.x; r1 += a.y;
                }
                float2 rr; rr.x = r0; rr.y = r1;
                *reinterpret_cast<float2*>(&g_Acc[px*64 + ch]) = rr;
                const float2 b = *reinterpret_cast<const float2*>(&g_base[px*64 + ch]);
                const float z0 = b.x + r0, z1 = b.y + r1;
                float2 zz; zz.x = z0; zz.y = z1;
                *reinterpret_cast<float2*>(&g_Y2[px*256 + (jblk+1)*64 + ch]) = zz;
                if (jblk < 2) {
                    const __half2 y = *reinterpret_cast<const __half2*>(
                        &g_Y1h[px*256 + (jblk+1)*64 + ch]);
                    const float dd0 = z0 - __half2float(y.x);
                    const float dd1 = z1 - __half2float(y.y);
                    *reinterpret_cast<__half2*>(&DOut[px*64 + ch]) =
                        __floats2half2_rn(dd0, dd1);
                }
            }
        }
    }
}

// ---------------------------------------------------------------------------
// Step3: per-pixel scalar recurrence (replaces 256 sequential 1x1 convs)
// ---------------------------------------------------------------------------
__global__ void __launch_bounds__(256)
step3_kernel(const float* __restrict__ x,
             const float* __restrict__ w3,
             const float* __restrict__ b3,
             float* __restrict__ out)
{
    __shared__ float sA[32][257];
    __shared__ float sw[256];
    const int tid = threadIdx.x;
    const size_t pBase = (size_t)blockIdx.x * 32;
    sw[tid] = w3[tid];

#pragma unroll
    for (int it = 0; it < 8; ++it) {
        const int g = it * 256 + tid;
        const int px = g >> 6;
        const int c = (g & 63) * 4;
        const float4 v = *reinterpret_cast<const float4*>(g_Y2 + (pBase + px)*256 + c);
        sA[px][c + 0] = fmaxf(v.x, 0.f);
        sA[px][c + 1] = fmaxf(v.y, 0.f);
        sA[px][c + 2] = fmaxf(v.z, 0.f);
        sA[px][c + 3] = fmaxf(v.w, 0.f);
    }
    __syncthreads();

    if (tid < 32) {
        float dot = 0.f;
#pragma unroll 8
        for (int c = 0; c < 256; ++c) dot = fmaf(sA[tid][c], sw[c], dot);
        const float bb = b3[0];
#pragma unroll 1
        for (int i = 0; i < 256; ++i) {
            const float a = sA[tid][i];
            const float z = dot + bb;
            sA[tid][i] = z;
            dot = fmaf(z - a, sw[i], dot);
        }
    }
    __syncthreads();

#pragma unroll
    for (int it = 0; it < 8; ++it) {
        const int g = it * 256 + tid;
        const int px = g >> 6;
        const int c = (g & 63) * 4;
        const float4 xv = *reinterpret_cast<const float4*>(x + (pBase + px)*256 + c);
        float4 r;
        r.x = sA[px][c + 0] + xv.x;
        r.y = sA[px][c + 1] + xv.y;
        r.z = sA[px][c + 2] + xv.z;
        r.w = sA[px][c + 3] + xv.w;
        *reinterpret_cast<float4*>(out + (pBase + px)*256 + c) = r;
    }
}

// ---------------------------------------------------------------------------
// Launch
// ---------------------------------------------------------------------------
extern "C" void kernel_launch(void* const* d_in, const int* in_sizes, int n_in,
                              void* d_out, int out_size)
{
    const float* x  = (const float*)d_in[0];
    const float* w1 = (const float*)d_in[1];
    const float* b1 = (const float*)d_in[2];
    const float* w2 = (const float*)d_in[3];
    const float* b2 = (const float*)d_in[4];
    const float* w3 = (const float*)d_in[5];
    const float* b3 = (const float*)d_in[6];
    float* out = (float*)d_out;

    __half *Y1h, *Dh0, *Dh1;
    float *ceff;
    cudaGetSymbolAddress((void**)&Y1h,  g_Y1h);
    cudaGetSymbolAddress((void**)&Dh0,  g_Dh0);
    cudaGetSymbolAddress((void**)&Dh1,  g_Dh1);
    cudaGetSymbolAddress((void**)&ceff, g_ceff);

    cudaFuncSetAttribute(compose_kernel,
                         cudaFuncAttributeMaxDynamicSharedMemorySize, COMPOSE_SMEM);
    cudaFuncSetAttribute(mma_p1,
                         cudaFuncAttributeMaxDynamicSharedMemorySize, SMEM1);
    cudaFuncSetAttribute(mma_p2,
                         cudaFuncAttributeMaxDynamicSharedMemorySize, SMEM3);
    cudaFuncSetAttribute(mma_corr,
                         cudaFuncAttributeMaxDynamicSharedMemorySize, SMEMC);

    // Phase 0: compose step1 weights; prep B tiles (xcvt fused into p1)
    compose_kernel<<<33, 256, COMPOSE_SMEM>>>(w1, b1);
    wprep_kernel<<<158, 256>>>(w2);

    // Phase 1: Y1 = relu(x @ Veff + ceff)   (converts x->fp16 inline)
    mma_p1<<<dim3(512, 4), 256, SMEM1>>>(x, ceff);

    // Phase 2: base = conv3x3(Y1, W2) + b2; Y2 blk0; D0
    mma_p2<<<512, 256, SMEM3>>>(Y1h, b2, Dh0);

    // Corrections: Z_{j+1} = base + sum_{m<=j} conv3x3(D_m, W2_blk_m)
    for (int j = 0; j < 3; ++j) {
        const __half* Ain = (j & 1) ? Dh1 : Dh0;
        __half*       Dn  = (j & 1) ? Dh0 : Dh1;
        mma_corr<<<512, 256, SMEMC>>>(Ain, Dn, j, (j > 0) ? 1 : 0);
    }

    // Phase 3: per-pixel recurrence + residual
    step3_kernel<<<2048, 256>>>(x, w3, b3, out);
}

// round 17
// speedup vs baseline: 1.2108x; 1.0427x over previous
#include <cuda_runtime.h>
#include <cuda_fp16.h>
#include <cstdint>
#include <cstddef>

#define PTOT (16*64*64)   // 65536 pixels, NHWC (C fastest)

// ---------------------------------------------------------------------------
// Device globals (no cudaMalloc allowed)
// ---------------------------------------------------------------------------
__device__ float g_Veff[256*256];
__device__ float g_ceff[256];
__device__ __half g_Y1h[(size_t)PTOT*256];
__device__ float g_Y2[(size_t)PTOT*256];
__device__ float g_base[(size_t)PTOT*64];
__device__ float g_Acc[(size_t)PTOT*64];
__device__ __half g_Dh0[(size_t)PTOT*64];
__device__ __half g_Dh1[(size_t)PTOT*64];
__device__ __half g_Bbuf[158*4096];           // fp16 hi/lo weight tiles

// ---------------------------------------------------------------------------
// PTX helpers (sm_80-compatible only; ptxas here targets plain sm_103)
// ---------------------------------------------------------------------------
__device__ __forceinline__ uint32_t s2u(const void* p) {
    uint32_t a;
    asm("{ .reg .u64 t; cvta.to.shared.u64 t, %1; cvt.u32.u64 %0, t; }"
        : "=r"(a) : "l"(p));
    return a;
}
#define SW128(o) ((uint32_t)(o) ^ (((uint32_t)(o) >> 3) & 0x70u))

__device__ __forceinline__ void cpa16(uint32_t dst, const void* src, bool valid) {
    asm volatile("cp.async.ca.shared.global [%0], [%1], 16, %2;"
                 :: "r"(dst), "l"(src), "r"(valid ? 16 : 0) : "memory");
}
__device__ __forceinline__ void cpa_commit() {
    asm volatile("cp.async.commit_group;" ::: "memory");
}
template<int N> __device__ __forceinline__ void cpa_wait() {
    asm volatile("cp.async.wait_group %0;" :: "n"(N) : "memory");
}

__device__ __forceinline__ void ldsm4(uint32_t* r, uint32_t addr) {
    asm volatile("ldmatrix.sync.aligned.m8n8.x4.shared.b16 {%0,%1,%2,%3}, [%4];"
                 : "=r"(r[0]), "=r"(r[1]), "=r"(r[2]), "=r"(r[3]) : "r"(addr));
}
__device__ __forceinline__ void mma_f16(float* c, const uint32_t* a, const uint32_t* b) {
    asm volatile(
        "mma.sync.aligned.m16n8k16.row.col.f32.f16.f16.f32 "
        "{%0,%1,%2,%3}, {%4,%5,%6,%7}, {%8,%9}, {%0,%1,%2,%3};"
        : "+f"(c[0]), "+f"(c[1]), "+f"(c[2]), "+f"(c[3])
        : "r"(a[0]), "r"(a[1]), "r"(a[2]), "r"(a[3]), "r"(b[0]), "r"(b[1]));
}
__device__ __forceinline__ uint32_t packh2(float a, float b) {
    __half2 h = __floats2half2_rn(a, b);
    return *reinterpret_cast<uint32_t*>(&h);
}

// ---------------------------------------------------------------------------
// Step1 composition in ONE kernel. One warp per row; state in registers.
// ---------------------------------------------------------------------------
#define COMPOSE_SMEM (64*256*4 + 64*4)
__global__ void __launch_bounds__(256)
compose_kernel(const float* __restrict__ w1, const float* __restrict__ b1)
{
    extern __shared__ float sh[];
    float* w1t = sh;
    float* b1s = sh + 64*256;
    const int tid = threadIdx.x;
    const int lane = tid & 31;

#pragma unroll
    for (int it = 0; it < 64; ++it) {
        const int id = it * 256 + tid;
        const int m = id >> 6, n = id & 63;
        w1t[n*256 + m] = w1[id];
    }
    if (tid < 64) b1s[tid] = b1[tid];
    __syncthreads();

    const int gw = blockIdx.x * 8 + (tid >> 5);
    if (gw > 256) return;
    const bool isC = (gw == 256);
    const int j = gw;

    float v[8], ex[2];
#pragma unroll
    for (int q = 0; q < 2; ++q)
        ex[q] = isC ? b1s[lane + 32*q] : w1[j*64 + lane + 32*q];
    v[0] = ex[0]; v[1] = ex[1];
    v[2]=v[3]=v[4]=v[5]=v[6]=v[7] = 0.f;

#pragma unroll
    for (int i = 1; i < 4; ++i) {
        const bool addEx = isC || (j >= 64 * i);
#pragma unroll 8
        for (int n = 0; n < 64; ++n) {
            float p = 0.f;
#pragma unroll
            for (int q = 0; q < 8; ++q)
                if (q < 2*i) p = fmaf(v[q], w1t[n*256 + lane + 32*q], p);
#pragma unroll
            for (int o = 16; o > 0; o >>= 1)
                p += __shfl_xor_sync(0xffffffffu, p, o);
            if (lane == (n & 31))
                v[2*i + (n >> 5)] = p + (addEx ? ex[n >> 5] : 0.f);
        }
    }

    if (isC) {
#pragma unroll
        for (int q = 0; q < 8; ++q) g_ceff[lane + 32*q] = v[q];
    } else {
#pragma unroll
        for (int q = 0; q < 8; ++q) g_Veff[j*256 + lane + 32*q] = v[q];
    }
}

// ---------------------------------------------------------------------------
// Weight prep: transpose + fp16-split + pre-swizzle all B tiles into g_Bbuf.
// ---------------------------------------------------------------------------
__global__ void wprep_kernel(const float* __restrict__ w2)
{
    const int b = blockIdx.x;
    const int tid = threadIdx.x;
    for (int it = 0; it < 16; ++it) {
        const int id = it * 256 + tid;
        const int n = id >> 6, k = id & 63;
        float val; int split;
        if (b < 32) {
            split = b >> 4; const int rem = b & 15;
            const int kc = rem >> 2, nt = rem & 3;
            val = g_Veff[(kc*64 + k)*256 + nt*64 + n];
        } else if (b < 104) {
            const int e = b - 32; split = e / 36; const int r = e % 36;
            const int t = r >> 2, kc = r & 3;
            val = w2[(size_t)t*16384 + (size_t)(kc*64 + k)*64 + n];
        } else {
            const int e = b - 104; const int j = e / 18; const int r = e % 18;
            split = r / 9; const int t = r % 9;
            val = w2[(size_t)t*16384 + (size_t)(j*64 + k)*64 + n];
        }
        const __half h = __float2half_rn(val);
        const __half l = __float2half_rn(val - __half2float(h));
        *reinterpret_cast<__half*>(
            reinterpret_cast<char*>(g_Bbuf) + (size_t)b*8192 + SW128(n*128 + k*2))
            = (split == 0) ? h : l;
    }
}

// ===========================================================================
// PHASE 1: Y1 = relu(x @ Veff + ceff)   (1x1 conv, K=256, grid 512 x 4)
// R16 configuration (355us best) — do not touch.
// ===========================================================================
#define SMEM1 81920
__device__ __forceinline__ uint32_t o1A(int buf) {
    return (uint32_t)buf*40960u;
}
__device__ __forceinline__ uint32_t o1B(int buf) {
    return (uint32_t)buf*40960u + 32768u;
}

__global__ void __launch_bounds__(256, 2)
mma_p1(const float* __restrict__ X,
       const float* __restrict__ bias)
{
    extern __shared__ char smem[];
    const uint32_t sb = s2u(smem);
    const int tid = threadIdx.x;
    const int lane = tid & 31;
    const int wid = tid >> 5;
    const int pxBase = blockIdx.x * 128;
    const int nt0 = blockIdx.y;
    const int n0 = nt0 * 64;
    const int wpx = (wid >> 1) * 32;
    const int wn  = (wid & 1) * 32;

    float c[2][4][4];
#pragma unroll
    for (int mt = 0; mt < 2; ++mt)
#pragma unroll
        for (int nt = 0; nt < 4; ++nt)
#pragma unroll
            for (int e = 0; e < 4; ++e) c[mt][nt][e] = 0.f;

    float4 xr[4][2];
    auto ldgA = [&](int cidx) {
#pragma unroll
        for (int it = 0; it < 4; ++it) {
            const int id = it * 256 + tid;
            const int r = id >> 3, u = id & 7;
            const long off = (long)(pxBase + r) * 256 + cidx*64 + u*8;
            xr[it][0] = *reinterpret_cast<const float4*>(X + off);
            xr[it][1] = *reinterpret_cast<const float4*>(X + off + 4);
        }
    };
    auto stsA = [&](int buf) {
#pragma unroll
        for (int it = 0; it < 4; ++it) {
            const int id = it * 256 + tid;
            const int r = id >> 3, u = id & 7;
            uint4 v;
            v.x = packh2(xr[it][0].x, xr[it][0].y);
            v.y = packh2(xr[it][0].z, xr[it][0].w);
            v.z = packh2(xr[it][1].x, xr[it][1].y);
            v.w = packh2(xr[it][1].z, xr[it][1].w);
            *reinterpret_cast<uint4*>(smem + o1A(buf) + SW128(r*128 + u*16)) = v;
        }
    };
    auto stageB = [&](int cidx, int buf) {
        const __half* bsH = g_Bbuf + (size_t)(cidx*4 + nt0) * 4096;
#pragma unroll
        for (int it = 0; it < 2; ++it) {
            const int id = it * 256 + tid;
            cpa16(sb + o1B(buf) + id*16, bsH + id*8, true);
        }
        cpa_commit();
    };

    ldgA(0);
    stageB(0, 0);
    stsA(0);

#pragma unroll 1
    for (int cc = 0; cc < 4; ++cc) {
        if (cc + 1 < 4) {
            ldgA(cc + 1);
            stageB(cc + 1, (cc + 1) & 1);
            cpa_wait<1>();
        } else {
            cpa_wait<0>();
        }
        __syncthreads();

        const int buf = cc & 1;
        const uint32_t aBa = sb + o1A(buf);
        const uint32_t bHi = sb + o1B(buf);

#pragma unroll
        for (int ks = 0; ks < 4; ++ks) {
            uint32_t ah[2][4], bh[4][2];
            {
                const int arow = wpx + ((lane >> 3) & 1) * 8 + (lane & 7);
                const int ak   = ks * 16 + (lane >> 4) * 8;
#pragma unroll
                for (int mt = 0; mt < 2; ++mt) {
                    const uint32_t asw = SW128((arow + mt*16) * 128 + ak * 2);
                    ldsm4(ah[mt], aBa + asw);
                }
            }
            {
                const int m = lane >> 3, r = lane & 7;
#pragma unroll
                for (int np = 0; np < 2; ++np) {
                    const int brow = wn + np*16 + (m >> 1) * 8 + r;
                    const int bk   = ks * 16 + (m & 1) * 8;
                    uint32_t rg[4];
                    ldsm4(rg, bHi + SW128(brow * 128 + bk * 2));
                    bh[np*2+0][0] = rg[0]; bh[np*2+0][1] = rg[1];
                    bh[np*2+1][0] = rg[2]; bh[np*2+1][1] = rg[3];
                }
            }
#pragma unroll
            for (int mt = 0; mt < 2; ++mt)
#pragma unroll
                for (int nt = 0; nt < 4; ++nt)
                    mma_f16(c[mt][nt], ah[mt], bh[nt]);
        }
        if (cc + 1 < 4) stsA((cc + 1) & 1);
        __syncthreads();
    }

    const int g = lane >> 2, tq = lane & 3;
#pragma unroll
    for (int mt = 0; mt < 2; ++mt)
#pragma unroll
        for (int rh = 0; rh < 2; ++rh) {
            const size_t px = (size_t)pxBase + wpx + mt*16 + rh*8 + g;
#pragma unroll
            for (int nt = 0; nt < 4; ++nt) {
                const int ch = wn + nt*8 + tq*2;
                const float r0 = fmaxf(c[mt][nt][rh*2+0] + bias[n0+ch],   0.f);
                const float r1 = fmaxf(c[mt][nt][rh*2+1] + bias[n0+ch+1], 0.f);
                *reinterpret_cast<__half2*>(&g_Y1h[px*256 + n0 + ch]) =
                    __floats2half2_rn(r0, r1);
            }
        }
}

// ===========================================================================
// PHASE 2: 3x3 conv, CIN=256, single-term fp16.
// WAVE FIX: single-buffered A halo (R12 proved the kc-prefetch was neutral)
// -> smem 50176, __launch_bounds__(256,4) -> 4 CTAs/SM -> grid 512 in ONE
// wave (capacity 592) instead of 2 (capacity 296, 73%-full second wave).
// smem: A halo [0,33792) B hi double-buffered [33792 + buf*8192) = 50176.
// ===========================================================================
#define SMEM3 50176
__device__ __forceinline__ uint32_t o3B(int buf) {
    return 33792u + (uint32_t)buf*8192u;
}

__global__ void __launch_bounds__(256, 4)
mma_p2(const __half* __restrict__ A,
       const float* __restrict__ bias,
       __half* __restrict__ DOut)
{
    extern __shared__ char smem[];
    const uint32_t sb = s2u(smem);
    const int tid = threadIdx.x;
    const int lane = tid & 31;
    const int wid = tid >> 5;
    const int pxBase = blockIdx.x * 128;
    const int y0 = (pxBase >> 6) & 63;
    const int img = pxBase >> 12;
    const int wpx = (wid >> 1) * 32;
    const int wn  = (wid & 1) * 32;

    float c[2][4][4];
#pragma unroll
    for (int mt = 0; mt < 2; ++mt)
#pragma unroll
        for (int nt = 0; nt < 4; ++nt)
#pragma unroll
            for (int e = 0; e < 4; ++e) c[mt][nt][e] = 0.f;

    auto stageA = [&](int kc) {
#pragma unroll 1
        for (int it = 0; it < 9; ++it) {
            const int id = it * 256 + tid;
            if (id < 2112) {
                const int r = id >> 3, u = id & 7;
                const int row = r / 66;
                const int xt  = r - row * 66;
                const int y = y0 - 1 + row;
                const int x = xt - 1;
                const bool valid = ((unsigned)y < 64u) && ((unsigned)x < 64u);
                const long off = valid
                    ? ((long)(img*4096 + y*64 + x) * 256 + kc*64 + u*8) : 0L;
                cpa16(sb + SW128(r*128 + u*16), A + off, valid);
            }
        }
    };

    auto stageB = [&](int kc, int t, int buf) {
        const __half* bsH = g_Bbuf + (size_t)(32 + t*4 + kc) * 4096;
#pragma unroll
        for (int it = 0; it < 2; ++it) {
            const int id = it * 256 + tid;
            cpa16(sb + o3B(buf) + id*16, bsH + id*8, true);
        }
    };

#pragma unroll 1
    for (int kc = 0; kc < 4; ++kc) {
        stageA(kc);
        stageB(kc, 0, 0);
        cpa_commit();
#pragma unroll 1
        for (int t = 0; t < 9; ++t) {
            if (t < 8) { stageB(kc, t + 1, (t + 1) & 1); cpa_commit(); cpa_wait<1>(); }
            else       { cpa_wait<0>(); }
            __syncthreads();

            const int dy = t / 3 - 1;
            const int dx = t % 3 - 1;
            const uint32_t bHi = sb + o3B(t & 1);

#pragma unroll
            for (int ks = 0; ks < 4; ++ks) {
                uint32_t ah[2][4], bh[4][2];
                {
                    const int arow = wpx + ((lane >> 3) & 1) * 8 + (lane & 7);
                    const int ak   = ks * 16 + (lane >> 4) * 8;
#pragma unroll
                    for (int mt = 0; mt < 2; ++mt) {
                        const int ar = arow + mt*16;
                        const int tpx = ((ar >> 6) + dy + 1) * 66 + (ar & 63) + dx + 1;
                        ldsm4(ah[mt], sb + SW128(tpx * 128 + ak * 2));
                    }
                }
                {
                    const int m = lane >> 3, r = lane & 7;
#pragma unroll
                    for (int np = 0; np < 2; ++np) {
                        const int brow = wn + np*16 + (m >> 1) * 8 + r;
                        const int bk   = ks * 16 + (m & 1) * 8;
                        uint32_t rg[4];
                        ldsm4(rg, bHi + SW128(brow * 128 + bk * 2));
                        bh[np*2+0][0] = rg[0]; bh[np*2+0][1] = rg[1];
                        bh[np*2+1][0] = rg[2]; bh[np*2+1][1] = rg[3];
                    }
                }
#pragma unroll
                for (int mt = 0; mt < 2; ++mt)
#pragma unroll
                    for (int nt = 0; nt < 4; ++nt)
                        mma_f16(c[mt][nt], ah[mt], bh[nt]);
            }
            __syncthreads();
        }
    }

    const int g = lane >> 2, tq = lane & 3;
#pragma unroll
    for (int mt = 0; mt < 2; ++mt) {
#pragma unroll
        for (int rh = 0; rh < 2; ++rh) {
            const size_t px = (size_t)pxBase + wpx + mt*16 + rh*8 + g;
#pragma unroll
            for (int nt = 0; nt < 4; ++nt) {
                const int ch = wn + nt*8 + tq*2;
                const float r0 = c[mt][nt][rh*2 + 0] + bias[ch];
                const float r1 = c[mt][nt][rh*2 + 1] + bias[ch+1];
                float2 rr; rr.x = r0; rr.y = r1;
                *reinterpret_cast<float2*>(&g_base[px*64 + ch]) = rr;
                *reinterpret_cast<float2*>(&g_Y2[px*256 + ch])  = rr;
                const __half2 y = *reinterpret_cast<const __half2*>(&g_Y1h[px*256 + ch]);
                const float dd0 = r0 - __half2float(y.x);
                const float dd1 = r1 - __half2float(y.y);
                *reinterpret_cast<__half2*>(&DOut[px*64 + ch]) =
                    __floats2half2_rn(dd0, dd1);
            }
        }
    }
}

// ===========================================================================
// CORRECTIONS: 3x3 conv, CIN=64, single-term fp16.
// WAVE FIX: __launch_bounds__(256,4) -> 4 CTAs/SM -> single wave for grid 512.
// ===========================================================================
#define SMEMC 50176
__device__ __forceinline__ uint32_t oCB(int buf) {
    return 33792u + (uint32_t)buf*8192u;
}

__global__ void __launch_bounds__(256, 4)
mma_corr(const __half* __restrict__ A,
         __half* __restrict__ DOut,
         int jblk, int accumPrev)
{
    extern __shared__ char smem[];
    const uint32_t sb = s2u(smem);
    const int tid = threadIdx.x;
    const int lane = tid & 31;
    const int wid = tid >> 5;
    const int pxBase = blockIdx.x * 128;
    const int y0 = (pxBase >> 6) & 63;
    const int img = pxBase >> 12;
    const int wpx = (wid >> 1) * 32;
    const int wn  = (wid & 1) * 32;

    float c[2][4][4];
#pragma unroll
    for (int mt = 0; mt < 2; ++mt)
#pragma unroll
        for (int nt = 0; nt < 4; ++nt)
#pragma unroll
            for (int e = 0; e < 4; ++e) c[mt][nt][e] = 0.f;

#pragma unroll 1
    for (int it = 0; it < 9; ++it) {
        const int id = it * 256 + tid;
        if (id < 2112) {
            const int r = id >> 3, u = id & 7;
            const int row = r / 66;
            const int xt  = r - row * 66;
            const int y = y0 - 1 + row;
            const int x = xt - 1;
            const bool valid = ((unsigned)y < 64u) && ((unsigned)x < 64u);
            const long off = valid
                ? ((long)(img*4096 + y*64 + x) * 64 + u*8) : 0L;
            cpa16(sb + SW128(r*128 + u*16), A + off, valid);
        }
    }

    auto stageB = [&](int t, int buf) {
        const __half* bsH = g_Bbuf + (size_t)(104 + jblk*18 + t) * 4096;
#pragma unroll
        for (int it = 0; it < 2; ++it) {
            const int id = it * 256 + tid;
            cpa16(sb + oCB(buf) + id*16, bsH + id*8, true);
        }
    };

    stageB(0, 0);
    cpa_commit();
#pragma unroll 1
    for (int t = 0; t < 9; ++t) {
        if (t < 8) { stageB(t + 1, (t + 1) & 1); cpa_commit(); cpa_wait<1>(); }
        else       { cpa_wait<0>(); }
        __syncthreads();

        const int dy = t / 3 - 1;
        const int dx = t % 3 - 1;
        const uint32_t bHi = sb + oCB(t & 1);

#pragma unroll
        for (int ks = 0; ks < 4; ++ks) {
            uint32_t ah[2][4], bh[4][2];
            {
                const int arow = wpx + ((lane >> 3) & 1) * 8 + (lane & 7);
                const int ak   = ks * 16 + (lane >> 4) * 8;
#pragma unroll
                for (int mt = 0; mt < 2; ++mt) {
                    const int ar = arow + mt*16;
                    const int tpx = ((ar >> 6) + dy + 1) * 66 + (ar & 63) + dx + 1;
                    ldsm4(ah[mt], sb + SW128(tpx * 128 + ak * 2));
                }
            }
            {
                const int m = lane >> 3, r = lane & 7;
#pragma unroll
                for (int np = 0; np < 2; ++np) {
                    const int brow = wn + np*16 + (m >> 1) * 8 + r;
                    const int bk   = ks * 16 + (m & 1) * 8;
                    uint32_t rg[4];
                    ldsm4(rg, bHi + SW128(brow * 128 + bk * 2));
                    bh[np*2+0][0] = rg[0]; bh[np*2+0][1] = rg[1];
                    bh[np*2+1][0] = rg[2]; bh[np*2+1][1] = rg[3];
                }
            }
#pragma unroll
            for (int mt = 0; mt < 2; ++mt)
#pragma unroll
                for (int nt = 0; nt < 4; ++nt)
                    mma_f16(c[mt][nt], ah[mt], bh[nt]);
        }
        __syncthreads();
    }

    const int g = lane >> 2, tq = lane & 3;
#pragma unroll
    for (int mt = 0; mt < 2; ++mt) {
#pragma unroll
        for (int rh = 0; rh < 2; ++rh) {
            const size_t px = (size_t)pxBase + wpx + mt*16 + rh*8 + g;
#pragma unroll
            for (int nt = 0; nt < 4; ++nt) {
                const int ch = wn + nt*8 + tq*2;
                float r0 = c[mt][nt][rh*2 + 0];
                float r1 = c[mt][nt][rh*2 + 1];
                if (accumPrev) {
                    const float2 a = *reinterpret_cast<const float2*>(&g_Acc[px*64 + ch]);
                    r0 += a.x; r1 += a.y;
                }
                float2 rr; rr.x = r0; rr.y = r1;
                *reinterpret_cast<float2*>(&g_Acc[px*64 + ch]) = rr;
                const float2 b = *reinterpret_cast<const float2*>(&g_base[px*64 + ch]);
                const float z0 = b.x + r0, z1 = b.y + r1;
                float2 zz; zz.x = z0; zz.y = z1;
                *reinterpret_cast<float2*>(&g_Y2[px*256 + (jblk+1)*64 + ch]) = zz;
                if (jblk < 2) {
                    const __half2 y = *reinterpret_cast<const __half2*>(
                        &g_Y1h[px*256 + (jblk+1)*64 + ch]);
                    const float dd0 = z0 - __half2float(y.x);
                    const float dd1 = z1 - __half2float(y.y);
                    *reinterpret_cast<__half2*>(&DOut[px*64 + ch]) =
                        __floats2half2_rn(dd0, dd1);
                }
            }
        }
    }
}

// ---------------------------------------------------------------------------
// Step3: per-pixel scalar recurrence (replaces 256 sequential 1x1 convs)
// ---------------------------------------------------------------------------
__global__ void __launch_bounds__(256)
step3_kernel(const float* __restrict__ x,
             const float* __restrict__ w3,
             const float* __restrict__ b3,
             float* __restrict__ out)
{
    __shared__ float sA[32][257];
    __shared__ float sw[256];
    const int tid = threadIdx.x;
    const size_t pBase = (size_t)blockIdx.x * 32;
    sw[tid] = w3[tid];

#pragma unroll
    for (int it = 0; it < 8; ++it) {
        const int g = it * 256 + tid;
        const int px = g >> 6;
        const int c = (g & 63) * 4;
        const float4 v = *reinterpret_cast<const float4*>(g_Y2 + (pBase + px)*256 + c);
        sA[px][c + 0] = fmaxf(v.x, 0.f);
        sA[px][c + 1] = fmaxf(v.y, 0.f);
        sA[px][c + 2] = fmaxf(v.z, 0.f);
        sA[px][c + 3] = fmaxf(v.w, 0.f);
    }
    __syncthreads();

    if (tid < 32) {
        float dot = 0.f;
#pragma unroll 8
        for (int c = 0; c < 256; ++c) dot = fmaf(sA[tid][c], sw[c], dot);
        const float bb = b3[0];
#pragma unroll 1
        for (int i = 0; i < 256; ++i) {
            const float a = sA[tid][i];
            const float z = dot + bb;
            sA[tid][i] = z;
            dot = fmaf(z - a, sw[i], dot);
        }
    }
    __syncthreads();

#pragma unroll
    for (int it = 0; it < 8; ++it) {
        const int g = it * 256 + tid;
        const int px = g >> 6;
        const int c = (g & 63) * 4;
        const float4 xv = *reinterpret_cast<const float4*>(x + (pBase + px)*256 + c);
        float4 r;
        r.x = sA[px][c + 0] + xv.x;
        r.y = sA[px][c + 1] + xv.y;
        r.z = sA[px][c + 2] + xv.z;
        r.w = sA[px][c + 3] + xv.w;
        *reinterpret_cast<float4*>(out + (pBase + px)*256 + c) = r;
    }
}

// ---------------------------------------------------------------------------
// Launch
// ---------------------------------------------------------------------------
extern "C" void kernel_launch(void* const* d_in, const int* in_sizes, int n_in,
                              void* d_out, int out_size)
{
    const float* x  = (const float*)d_in[0];
    const float* w1 = (const float*)d_in[1];
    const float* b1 = (const float*)d_in[2];
    const float* w2 = (const float*)d_in[3];
    const float* b2 = (const float*)d_in[4];
    const float* w3 = (const float*)d_in[5];
    const float* b3 = (const float*)d_in[6];
    float* out = (float*)d_out;

    __half *Y1h, *Dh0, *Dh1;
    float *ceff;
    cudaGetSymbolAddress((void**)&Y1h,  g_Y1h);
    cudaGetSymbolAddress((void**)&Dh0,  g_Dh0);
    cudaGetSymbolAddress((void**)&Dh1,  g_Dh1);
    cudaGetSymbolAddress((void**)&ceff, g_ceff);

    cudaFuncSetAttribute(compose_kernel,
                         cudaFuncAttributeMaxDynamicSharedMemorySize, COMPOSE_SMEM);
    cudaFuncSetAttribute(mma_p1,
                         cudaFuncAttributeMaxDynamicSharedMemorySize, SMEM1);
    cudaFuncSetAttribute(mma_p2,
                         cudaFuncAttributeMaxDynamicSharedMemorySize, SMEM3);
    cudaFuncSetAttribute(mma_corr,
                         cudaFuncAttributeMaxDynamicSharedMemorySize, SMEMC);

    // Phase 0: compose step1 weights; prep B tiles (xcvt fused into p1)
    compose_kernel<<<33, 256, COMPOSE_SMEM>>>(w1, b1);
    wprep_kernel<<<158, 256>>>(w2);

    // Phase 1: Y1 = relu(x @ Veff + ceff)   (converts x->fp16 inline)
    mma_p1<<<dim3(512, 4), 256, SMEM1>>>(x, ceff);

    // Phase 2: base = conv3x3(Y1, W2) + b2; Y2 blk0; D0
    mma_p2<<<512, 256, SMEM3>>>(Y1h, b2, Dh0);

    // Corrections: Z_{j+1} = base + sum_{m<=j} conv3x3(D_m, W2_blk_m)
    for (int j = 0; j < 3; ++j) {
        const __half* Ain = (j & 1) ? Dh1 : Dh0;
        __half*       Dn  = (j & 1) ? Dh0 : Dh1;
        mma_corr<<<512, 256, SMEMC>>>(Ain, Dn, j, (j > 0) ? 1 : 0);
    }

    // Phase 3: per-pixel recurrence + residual
    step3_kernel<<<2048, 256>>>(x, w3, b3, out);
}